// round 13
// baseline (speedup 1.0000x reference)
#include <cuda_runtime.h>
#include <cuda_fp16.h>
#include <cstdint>

#define BB   32
#define CC   128
#define DD   256
#define FF_  512
#define HWN  4096
#define EPS  1e-5f

// ---------------- scratch ----------------
__device__ float g_p  [(size_t)BB * DD  * HWN];    // token tensor fp32
__device__ float g_kv [(size_t)BB * 512 * HWN];    // k|v fp32 (also dwconv temp)
__device__ float g_ctx[BB * 4 * DD];
__device__ float g_s2[CC], g_b2[CC];

// transposed fp16 hi/lo activation planes, [b][col][k]
__device__ __half g_zth[(size_t)BB * HWN * DD ];
__device__ __half g_ztl[(size_t)BB * HWN * DD ];
__device__ __half g_hth[(size_t)BB * HWN * FF_];
__device__ __half g_htl[(size_t)BB * HWN * FF_];
__device__ __half g_yth[(size_t)BB * HWN * CC ];
__device__ __half g_ytl[(size_t)BB * HWN * CC ];

#define WTOT 983040
__device__ __half g_whi[WTOT];          // single-plane fp16 weights
#define OFF_C1    0
#define LSTRIDE   458752
#define OFF_KV(l)  (32768 + (l) * LSTRIDE)
#define OFF_OUT(l) (OFF_KV(l) + 131072)
#define OFF_F1(l)  (OFF_KV(l) + 196608)
#define OFF_F2(l)  (OFF_KV(l) + 327680)
#define OFF_PROJ  (32768 + 2 * LSTRIDE)

__device__ __forceinline__ void split_pair(float a, float b, uint32_t& h, uint32_t& l) {
    __half ha = __float2half_rn(a), hb = __float2half_rn(b);
    h = (uint32_t)__half_as_ushort(ha) | ((uint32_t)__half_as_ushort(hb) << 16);
    __half la = __float2half_rn(a - __half2float(ha));
    __half lb = __float2half_rn(b - __half2float(hb));
    l = (uint32_t)__half_as_ushort(la) | ((uint32_t)__half_as_ushort(lb) << 16);
}
__device__ __forceinline__ float2 up2(uint32_t v) {
    __half2 t = *reinterpret_cast<const __half2*>(&v);
    return __half22float2(t);
}

// ---------------- wsplit_all: all weights (fp16) + BN2 prep, ONE launch -----
struct WArgs {
    const float* src[10];
    int K[10];
    int off[10];
    int row0[11];
};
__global__ void __launch_bounds__(128) wsplit_all(
    WArgs a, const float* bg, const float* bb, const float* bm, const float* bv)
{
    int blk = blockIdx.x;
    if (blk == 3456) {
        int i = threadIdx.x;
        if (i < CC) {
            float s = bg[i] * rsqrtf(bv[i] + EPS);
            g_s2[i] = s; g_b2[i] = bb[i] - bm[i] * s;
        }
        return;
    }
    int s = 0;
    while (blk >= a.row0[s + 1]) s++;
    int row = blk - a.row0[s];
    int K = a.K[s];
    const float* src = a.src[s] + (size_t)row * K;
    __half* dh = g_whi + a.off[s] + (size_t)row * K;
    for (int k = threadIdx.x; k < K; k += 128)
        dh[k] = __float2half_rn(src[k]);
}

// ---------------- dwconv3x3 + BN1 + leaky (fp32 temp) ----------------
__global__ void __launch_bounds__(256) dwconv_k(
    const float* __restrict__ x, const float* __restrict__ w,
    const float* __restrict__ bg, const float* __restrict__ bbias,
    const float* __restrict__ bm, const float* __restrict__ bv, float* __restrict__ yout)
{
    int b = blockIdx.z, c = blockIdx.y;
    int idx = blockIdx.x * 256 + threadIdx.x;
    __shared__ float ws[9]; __shared__ float sc, sh;
    if (threadIdx.x < 9) ws[threadIdx.x] = w[c * 9 + threadIdx.x];
    if (threadIdx.x == 0) {
        float s = bg[c] * rsqrtf(bv[c] + EPS);
        sc = s; sh = bbias[c] - bm[c] * s;
    }
    __syncthreads();
    int h = idx >> 6, wq = idx & 63;
    const float* xp = x + ((size_t)b * CC + c) * HWN;
    float acc = 0.f;
#pragma unroll
    for (int dh = 0; dh < 3; dh++) {
        int hh = h + dh - 1;
        if (hh < 0 || hh >= 64) continue;
#pragma unroll
        for (int dw = 0; dw < 3; dw++) {
            int w2 = wq + dw - 1;
            if (w2 < 0 || w2 >= 64) continue;
            acc = fmaf(xp[hh * 64 + w2], ws[dh * 3 + dw], acc);
        }
    }
    float o = acc * sc + sh;
    o = (o > 0.f) ? o : 0.1f * o;
    yout[((size_t)b * CC + c) * HWN + idx] = o;
}

// ---------------- y fp32 [c][pix] -> yt planes [pix][128] ----------------
__global__ void __launch_bounds__(256) ypack_k(const float* __restrict__ y)
{
    int b = blockIdx.y, tx = threadIdx.x, ty = threadIdx.y;
    int p0 = blockIdx.x * 32;
    __shared__ float sy[128][33];
    for (int ct = 0; ct < 4; ct++)
#pragma unroll
        for (int q = 0; q < 4; q++) {
            int c = ct * 32 + ty * 4 + q;
            sy[c][tx] = y[((size_t)b * CC + c) * HWN + p0 + tx];
        }
    __syncthreads();
    uint32_t wh[8], wl[8];
#pragma unroll
    for (int j = 0; j < 16; j += 2)
        split_pair(sy[ty * 16 + j][tx], sy[ty * 16 + j + 1][tx], wh[j >> 1], wl[j >> 1]);
    size_t o = ((size_t)b * HWN + p0 + tx) * CC + ty * 16;
    uint4* dh = reinterpret_cast<uint4*>(g_yth + o);
    uint4* dl = reinterpret_cast<uint4*>(g_ytl + o);
    dh[0] = make_uint4(wh[0], wh[1], wh[2], wh[3]);
    dh[1] = make_uint4(wh[4], wh[5], wh[6], wh[7]);
    dl[0] = make_uint4(wl[0], wl[1], wl[2], wl[3]);
    dl[1] = make_uint4(wl[4], wl[5], wl[6], wl[7]);
}

// ---------------- colstats + LN -> z planes [col][256] ----------------
__global__ void __launch_bounds__(256) colstats_k(
    const float* __restrict__ p,
    const float* __restrict__ lng, const float* __restrict__ lnb)
{
    int b = blockIdx.y, tx = threadIdx.x, ty = threadIdx.y;
    int col = blockIdx.x * 32 + tx;
    int lt = ty * 32 + tx;
    __shared__ float sg[256], sb[256];
    sg[lt] = lng[lt]; sb[lt] = lnb[lt];
    size_t base = (size_t)b * DD * HWN + col;
    float vals[32], s = 0.f, s2 = 0.f;
#pragma unroll
    for (int j = 0; j < 32; j++) {
        float v = p[base + ((size_t)(ty * 32 + j) << 12)];
        vals[j] = v; s += v; s2 = fmaf(v, v, s2);
    }
    __shared__ float sh1[8][32], sh2[8][32], smean[32], srstd[32];
    sh1[ty][tx] = s; sh2[ty][tx] = s2;
    __syncthreads();
    if (ty == 0) {
        float a = 0.f, a2 = 0.f;
#pragma unroll
        for (int k = 0; k < 8; k++) { a += sh1[k][tx]; a2 += sh2[k][tx]; }
        float mean = a * (1.f / DD);
        smean[tx] = mean;
        srstd[tx] = rsqrtf(a2 * (1.f / DD) - mean * mean + EPS);
    }
    __syncthreads();
    float mean = smean[tx], rstd = srstd[tx];
    uint32_t wh[16], wl[16];
#pragma unroll
    for (int j = 0; j < 32; j += 2) {
        int d = ty * 32 + j;
        float z0 = (vals[j]     - mean) * rstd * sg[d]     + sb[d];
        float z1 = (vals[j + 1] - mean) * rstd * sg[d + 1] + sb[d + 1];
        split_pair(z0, z1, wh[j >> 1], wl[j >> 1]);
    }
    size_t o = ((size_t)b * HWN + col) * DD + ty * 32;
    uint4* dh = reinterpret_cast<uint4*>(g_zth + o);
    uint4* dl = reinterpret_cast<uint4*>(g_ztl + o);
#pragma unroll
    for (int q = 0; q < 4; q++) {
        dh[q] = make_uint4(wh[4*q], wh[4*q+1], wh[4*q+2], wh[4*q+3]);
        dl[q] = make_uint4(wl[4*q], wl[4*q+1], wl[4*q+2], wl[4*q+3]);
    }
}

// ---------------- relu(v)*ctx -> z planes (reused) [n][256] ----------------
__global__ void __launch_bounds__(256) vctx_k()
{
    int b = blockIdx.y, tx = threadIdx.x, ty = threadIdx.y;
    int n0 = blockIdx.x * 32;
    int pq = n0 >> 10;
    __shared__ float sv[256][33];
    for (int dt = 0; dt < 8; dt++)
#pragma unroll
        for (int q = 0; q < 4; q++) {
            int d = dt * 32 + ty * 4 + q;
            float v = g_kv[((size_t)b * 512 + 256 + d) * HWN + n0 + tx];
            sv[d][tx] = fmaxf(v, 0.f) * g_ctx[(b << 10) + (pq << 8) + d];
        }
    __syncthreads();
    uint32_t wh[16], wl[16];
#pragma unroll
    for (int j = 0; j < 32; j += 2)
        split_pair(sv[ty * 32 + j][tx], sv[ty * 32 + j + 1][tx], wh[j >> 1], wl[j >> 1]);
    size_t o = ((size_t)b * HWN + n0 + tx) * DD + ty * 32;
    uint4* dh = reinterpret_cast<uint4*>(g_zth + o);
    uint4* dl = reinterpret_cast<uint4*>(g_ztl + o);
#pragma unroll
    for (int q = 0; q < 4; q++) {
        dh[q] = make_uint4(wh[4*q], wh[4*q+1], wh[4*q+2], wh[4*q+3]);
        dl[q] = make_uint4(wl[4*q], wl[4*q+1], wl[4*q+2], wl[4*q+3]);
    }
}

// ---------------- q-GEMV + softmax + ctx ----------------
__global__ void __launch_bounds__(256) qsoftctx_k(
    const float* __restrict__ wq, const float* __restrict__ qb)
{
    __shared__ float sprob[1024], wqs[256], red[256];
    int tid = threadIdx.x;
    int b = blockIdx.x >> 2, pq = blockIdx.x & 3;
    wqs[tid] = wq[tid];
    __syncthreads();
    float q0 = qb[0], qv[4];
#pragma unroll
    for (int r = 0; r < 4; r++) {
        int n = tid + (r << 8);
        size_t base = ((size_t)b * HWN + pq * 1024 + n) * DD;
        const uint4* zh = reinterpret_cast<const uint4*>(g_zth + base);
        const uint4* zl = reinterpret_cast<const uint4*>(g_ztl + base);
        float acc = q0;
#pragma unroll 4
        for (int i = 0; i < 32; i++) {
            uint4 H = zh[i], L = zl[i];
            const float* w8 = wqs + i * 8;
            float2 h0 = up2(H.x), l0 = up2(L.x), h1 = up2(H.y), l1 = up2(L.y);
            float2 h2 = up2(H.z), l2 = up2(L.z), h3 = up2(H.w), l3 = up2(L.w);
            acc = fmaf(w8[0], h0.x + l0.x, acc); acc = fmaf(w8[1], h0.y + l0.y, acc);
            acc = fmaf(w8[2], h1.x + l1.x, acc); acc = fmaf(w8[3], h1.y + l1.y, acc);
            acc = fmaf(w8[4], h2.x + l2.x, acc); acc = fmaf(w8[5], h2.y + l2.y, acc);
            acc = fmaf(w8[6], h3.x + l3.x, acc); acc = fmaf(w8[7], h3.y + l3.y, acc);
        }
        qv[r] = acc;
    }
    float lm = fmaxf(fmaxf(qv[0], qv[1]), fmaxf(qv[2], qv[3]));
    red[tid] = lm; __syncthreads();
    for (int s = 128; s > 0; s >>= 1) { if (tid < s) red[tid] = fmaxf(red[tid], red[tid+s]); __syncthreads(); }
    float gm = red[0]; __syncthreads();
    float e[4], ls = 0.f;
#pragma unroll
    for (int r = 0; r < 4; r++) { e[r] = __expf(qv[r] - gm); ls += e[r]; }
    red[tid] = ls; __syncthreads();
    for (int s = 128; s > 0; s >>= 1) { if (tid < s) red[tid] += red[tid+s]; __syncthreads(); }
    float inv = 1.f / red[0];
#pragma unroll
    for (int r = 0; r < 4; r++) sprob[tid + (r << 8)] = e[r] * inv;
    __syncthreads();
    int warp = tid >> 5, lane = tid & 31;
    for (int d = warp; d < 256; d += 8) {
        const float* kr = g_kv + ((size_t)b * 512 + d) * HWN + pq * 1024;
        float acc = 0.f;
#pragma unroll 8
        for (int n = lane; n < 1024; n += 32) acc = fmaf(kr[n], sprob[n], acc);
#pragma unroll
        for (int o = 16; o > 0; o >>= 1) acc += __shfl_down_sync(0xffffffffu, acc, o);
        if (lane == 0) g_ctx[(b << 10) + (pq << 8) + d] = acc;
    }
}

// ============================================================================
// fp16 2-product GEMM v13: 256 threads, 8 warps of 64m x 32n (2m x 4n groups)
// CTA 128x128, k-tile 32, cp.async 3-stage; smem stage 24KB: A | Bh | Bl
// ============================================================================
__device__ __forceinline__ uint32_t smem_u32(const void* p) {
    uint32_t a;
    asm("{ .reg .u64 t; cvta.to.shared.u64 t, %1; cvt.u32.u64 %0, t; }" : "=r"(a) : "l"(p));
    return a;
}
#define LDSM4(R, A)                                                            \
    asm volatile("ldmatrix.sync.aligned.m8n8.x4.shared.b16 {%0,%1,%2,%3}, [%4];" \
        : "=r"((R)[0]), "=r"((R)[1]), "=r"((R)[2]), "=r"((R)[3]) : "r"(A))
#define HMMA32(D, A, B0, B1)                                                   \
    asm volatile("mma.sync.aligned.m16n8k16.row.col.f32.f16.f16.f32 "          \
        "{%0,%1,%2,%3},{%4,%5,%6,%7},{%8,%9},{%0,%1,%2,%3};"                   \
        : "+f"((D)[0]), "+f"((D)[1]), "+f"((D)[2]), "+f"((D)[3])               \
        : "r"((A)[0]), "r"((A)[1]), "r"((A)[2]), "r"((A)[3]), "r"(B0), "r"(B1))
#define CPA(D, S) asm volatile("cp.async.cg.shared.global [%0], [%1], 16;" :: "r"(D), "l"(S))

enum { E_KV = 0, E_RESID = 1, E_PERM_P = 2, E_OUT = 3, E_H = 4 };
#define G13_SMEM 73728   // 3 stages x 24KB

__device__ __forceinline__ uint32_t swz(int r, int c) {
    return (uint32_t)(r * 64 + ((c ^ ((r >> 1) & 3)) << 4));
}

template<int EP>
__global__ void __launch_bounds__(256, 2) gemm13(
    int woff, const __half* __restrict__ Bhp, const __half* __restrict__ Blp,
    float* __restrict__ Y, const float* __restrict__ bias, int M, int K)
{
    extern __shared__ __align__(16) char smc[];
    const uint32_t sma = smem_u32(smc);
    const int tid = threadIdx.x, wid = tid >> 5, lane = tid & 31;
    const int gid = lane >> 2, tig = lane & 3;
    const int b = blockIdx.z, colT = blockIdx.x << 7, rowT = blockIdx.y << 7;
    const int mw = (wid & 1) << 6;    // 0 / 64
    const int nw = (wid >> 1) << 5;   // 0 / 32 / 64 / 96
    const int nT = K >> 5;

    const __half* gAh = g_whi + woff;

    float acc[4][4][4];
#pragma unroll
    for (int i = 0; i < 4; i++)
#pragma unroll
        for (int j = 0; j < 4; j++)
#pragma unroll
            for (int k = 0; k < 4; k++) acc[i][j][k] = 0.f;

    auto issue = [&](int c) {
        uint32_t base = sma + (c % 3) * 24576;
        int k0 = c << 5;
#pragma unroll
        for (int i = 0; i < 2; i++) {
            int sid = tid * 2 + i;
            int r = sid >> 2, pc = sid & 3;
            uint32_t sw = swz(r, pc);
            size_t ga = (size_t)(rowT + r) * K + k0 + pc * 8;
            size_t gb = ((size_t)b * HWN + colT + r) * K + k0 + pc * 8;
            CPA(base + sw,         gAh + ga);
            CPA(base + 8192 + sw,  Bhp + gb);
            CPA(base + 16384 + sw, Blp + gb);
        }
        asm volatile("cp.async.commit_group;");
    };

    issue(0);
    if (nT > 1) issue(1);
    for (int c = 0; c < nT; c++) {
        if (c + 1 < nT) asm volatile("cp.async.wait_group 1;");
        else            asm volatile("cp.async.wait_group 0;");
        __syncthreads();
        if (c + 2 < nT) issue(c + 2);
        uint32_t sb = sma + (c % 3) * 24576;
#pragma unroll
        for (int h = 0; h < 2; h++) {
            int cc = h * 2 + (lane >> 4);
            uint32_t Ah[4][4];
#pragma unroll
            for (int mi = 0; mi < 4; mi++) {
                int r = mw + mi * 16 + (lane & 15);
                LDSM4(Ah[mi], sb + swz(r, cc));
            }
#pragma unroll
            for (int p = 0; p < 2; p++) {
                uint32_t Bh[4], Bl[4];
                int r = nw + p * 16 + (lane & 15);
                uint32_t ad = sb + 8192 + swz(r, cc);
                LDSM4(Bh, ad);
                LDSM4(Bl, ad + 8192);
#pragma unroll
                for (int mi = 0; mi < 4; mi++)
#pragma unroll
                    for (int q = 0; q < 2; q++) {
                        int ni = p * 2 + q;
                        HMMA32(acc[mi][ni], Ah[mi], Bh[q], Bh[q + 2]);
                        HMMA32(acc[mi][ni], Ah[mi], Bl[q], Bl[q + 2]);
                    }
            }
        }
    }

    // ---- epilogue ----
    if (EP == E_H) {
        __syncthreads();
        __half* trh = reinterpret_cast<__half*>(smc);
        __half* trl = trh + 128 * 136;
#pragma unroll
        for (int mi = 0; mi < 4; mi++) {
            float bi0 = bias[rowT + mw + mi * 16 + gid];
            float bi1 = bias[rowT + mw + mi * 16 + gid + 8];
#pragma unroll
            for (int ni = 0; ni < 4; ni++)
#pragma unroll
                for (int r = 0; r < 4; r++) {
                    float v = acc[mi][ni][r] + ((r >> 1) ? bi1 : bi0);
                    v = (v > 0.f) ? v : 0.1f * v;
                    int ml = mw + mi * 16 + gid + (r >> 1) * 8;
                    int nl = nw + ni * 8 + tig * 2 + (r & 1);
                    __half hh = __float2half_rn(v);
                    trh[nl * 136 + ml] = hh;
                    trl[nl * 136 + ml] = __float2half_rn(v - __half2float(hh));
                }
        }
        __syncthreads();
        int nl = tid >> 1, qt = tid & 1;
        const uint4* s1 = reinterpret_cast<const uint4*>(trh + nl * 136 + qt * 64);
        const uint4* s2 = reinterpret_cast<const uint4*>(trl + nl * 136 + qt * 64);
        size_t o = ((size_t)b * HWN + colT + nl) * FF_ + rowT + qt * 64;
        uint4* d1 = reinterpret_cast<uint4*>(g_hth + o);
        uint4* d2 = reinterpret_cast<uint4*>(g_htl + o);
#pragma unroll
        for (int j = 0; j < 8; j++) { d1[j] = s1[j]; d2[j] = s2[j]; }
        return;
    }

#pragma unroll
    for (int mi = 0; mi < 4; mi++)
#pragma unroll
        for (int r2 = 0; r2 < 2; r2++) {
            int m = rowT + mw + mi * 16 + gid + r2 * 8;
            float bi = (EP == E_OUT) ? 0.f : bias[m];
#pragma unroll
            for (int ni = 0; ni < 4; ni++) {
                int c0 = colT + nw + ni * 8 + tig * 2;
                float v0 = acc[mi][ni][r2 * 2 + 0] + bi;
                float v1 = acc[mi][ni][r2 * 2 + 1] + bi;
                if (EP == E_OUT) {
                    float rs = g_s2[m], rb = g_b2[m];
                    v0 = v0 * rs + rb; v1 = v1 * rs + rb;
                    float* yb = Y + ((size_t)b * CC + m) * HWN;
#pragma unroll
                    for (int cb = 0; cb < 2; cb++) {
                        int col = c0 + cb;
                        int pq = col >> 10, n = col & 1023;
                        int h = ((n >> 5) << 1) | (pq >> 1);
                        int w2 = ((n & 31) << 1) | (pq & 1);
                        yb[h * 64 + w2] = cb ? v1 : v0;
                    }
                } else if (EP == E_PERM_P) {
#pragma unroll
                    for (int cb = 0; cb < 2; cb++) {
                        int col = c0 + cb;
                        int h = col >> 6, w = col & 63;
                        int pc2 = ((((h & 1) << 1) | (w & 1)) << 10) | ((h >> 1) << 5) | (w >> 1);
                        Y[((size_t)b * M + m) * HWN + pc2] = cb ? v1 : v0;
                    }
                } else {
                    float2* yp = reinterpret_cast<float2*>(&Y[((size_t)b * M + m) * HWN + c0]);
                    if (EP == E_RESID) {
                        float2 o = *yp;
                        o.x += v0; o.y += v1;
                        *yp = o;
                    } else {
                        *yp = make_float2(v0, v1);
                    }
                }
            }
        }
}

// ---------------- host ----------------
template<int EP>
static void launch13(int woff, const __half* Bh, const __half* Bl,
                     float* Y, const float* bias, int M, int K)
{
    cudaFuncSetAttribute(gemm13<EP>, cudaFuncAttributeMaxDynamicSharedMemorySize, G13_SMEM);
    gemm13<EP><<<dim3(32, M / 128, BB), 256, G13_SMEM>>>(woff, Bh, Bl, Y, bias, M, K);
}

extern "C" void kernel_launch(void* const* d_in, const int* in_sizes, int n_in,
                              void* d_out, int out_size)
{
    const float* x     = (const float*)d_in[0];
    const float* dw_w  = (const float*)d_in[1];
    const float* bn1_g = (const float*)d_in[2];
    const float* bn1_b = (const float*)d_in[3];
    const float* bn1_m = (const float*)d_in[4];
    const float* bn1_v = (const float*)d_in[5];
    const float* c1_w  = (const float*)d_in[6];
    const float* c1_b  = (const float*)d_in[7];
    const float* ln1_g = (const float*)d_in[8];
    const float* ln1_b = (const float*)d_in[9];
    const float* qkv_w = (const float*)d_in[10];
    const float* qkv_b = (const float*)d_in[11];
    const float* out_w = (const float*)d_in[12];
    const float* out_b = (const float*)d_in[13];
    const float* ln2_g = (const float*)d_in[14];
    const float* ln2_b = (const float*)d_in[15];
    const float* f1_w  = (const float*)d_in[16];
    const float* f1_b  = (const float*)d_in[17];
    const float* f2_w  = (const float*)d_in[18];
    const float* f2_b  = (const float*)d_in[19];
    const float* lnf_g = (const float*)d_in[20];
    const float* lnf_b = (const float*)d_in[21];
    const float* projw = (const float*)d_in[22];
    const float* bn2_g = (const float*)d_in[23];
    const float* bn2_b = (const float*)d_in[24];
    const float* bn2_m = (const float*)d_in[25];
    const float* bn2_v = (const float*)d_in[26];
    float* out = (float*)d_out;

    void* vp;
    cudaGetSymbolAddress(&vp, g_p);   float* p  = (float*)vp;
    cudaGetSymbolAddress(&vp, g_kv);  float* kv = (float*)vp;
    cudaGetSymbolAddress(&vp, g_zth); __half* zth = (__half*)vp;
    cudaGetSymbolAddress(&vp, g_ztl); __half* ztl = (__half*)vp;
    cudaGetSymbolAddress(&vp, g_hth); __half* hth = (__half*)vp;
    cudaGetSymbolAddress(&vp, g_htl); __half* htl = (__half*)vp;
    cudaGetSymbolAddress(&vp, g_yth); __half* yth = (__half*)vp;
    cudaGetSymbolAddress(&vp, g_ytl); __half* ytl = (__half*)vp;

    // single weight-convert launch (also folds BN2)
    WArgs wa;
    const float* qw0 = qkv_w;
    const float* qw1 = qkv_w + (size_t)513 * DD;
    const float* srcs[10] = {
        c1_w,
        qw0 + DD, out_w, f1_w, f2_w,
        qw1 + DD, out_w + (size_t)DD * DD, f1_w + (size_t)FF_ * DD, f2_w + (size_t)DD * FF_,
        projw };
    int Ks[10]   = {128, 256, 256, 256, 512, 256, 256, 256, 512, 256};
    int offs[10] = {OFF_C1, OFF_KV(0), OFF_OUT(0), OFF_F1(0), OFF_F2(0),
                    OFF_KV(1), OFF_OUT(1), OFF_F1(1), OFF_F2(1), OFF_PROJ};
    int rows[10] = {256, 512, 256, 512, 256, 512, 256, 512, 256, 128};
    int acc = 0;
    for (int i = 0; i < 10; i++) {
        wa.src[i] = srcs[i]; wa.K[i] = Ks[i]; wa.off[i] = offs[i];
        wa.row0[i] = acc; acc += rows[i];
    }
    wa.row0[10] = acc;  // 3456
    wsplit_all<<<3457, 128>>>(wa, bn2_g, bn2_b, bn2_m, bn2_v);

    dwconv_k<<<dim3(16, CC, BB), 256>>>(x, dw_w, bn1_g, bn1_b, bn1_m, bn1_v, kv);
    ypack_k<<<dim3(128, BB), dim3(32, 8)>>>(kv);

    // c1: p = patchify(W_c1 @ y + b)
    launch13<E_PERM_P>(OFF_C1, yth, ytl, p, c1_b, DD, 128);

    for (int l = 0; l < 2; l++) {
        const float* qw  = qkv_w + (size_t)l * 513 * DD;
        const float* qbi = qkv_b + l * 513;

        colstats_k<<<dim3(128, BB), dim3(32, 8)>>>(p, ln1_g + l * DD, ln1_b + l * DD);
        launch13<E_KV>(OFF_KV(l), zth, ztl, kv, qbi + 1, 512, 256);
        qsoftctx_k<<<128, 256>>>(qw, qbi);
        vctx_k<<<dim3(128, BB), dim3(32, 8)>>>();
        launch13<E_RESID>(OFF_OUT(l), zth, ztl, p, out_b + l * DD, DD, 256);

        colstats_k<<<dim3(128, BB), dim3(32, 8)>>>(p, ln2_g + l * DD, ln2_b + l * DD);
        launch13<E_H>(OFF_F1(l), zth, ztl, nullptr, f1_b + l * FF_, FF_, 256);
        launch13<E_RESID>(OFF_F2(l), hth, htl, p, f2_b + l * DD, DD, 512);
    }

    colstats_k<<<dim3(128, BB), dim3(32, 8)>>>(p, lnf_g, lnf_b);
    launch13<E_OUT>(OFF_PROJ, zth, ztl, out, nullptr, CC, 256);
}

// round 14
// speedup vs baseline: 1.2220x; 1.2220x over previous
#include <cuda_runtime.h>
#include <cuda_fp16.h>
#include <cstdint>

#define BB   32
#define CC   128
#define DD   256
#define FF_  512
#define HWN  4096
#define EPS  1e-5f

// ---------------- scratch ----------------
__device__ float g_p  [(size_t)BB * DD  * HWN];    // token tensor fp32
__device__ float g_kv [(size_t)BB * 512 * HWN];    // k|v fp32 (also dwconv temp)
__device__ float g_ctx[BB * 4 * DD];
__device__ float g_s2[CC], g_b2[CC];

// transposed fp16 hi/lo activation planes, [b][col][k]
__device__ __half g_zth[(size_t)BB * HWN * DD ];
__device__ __half g_ztl[(size_t)BB * HWN * DD ];
__device__ __half g_hth[(size_t)BB * HWN * FF_];   // h: single plane
__device__ __half g_yth[(size_t)BB * HWN * CC ];
__device__ __half g_ytl[(size_t)BB * HWN * CC ];

#define WTOT 983040
__device__ __half g_whi[WTOT];          // single-plane fp16 weights
#define OFF_C1    0
#define LSTRIDE   458752
#define OFF_KV(l)  (32768 + (l) * LSTRIDE)
#define OFF_OUT(l) (OFF_KV(l) + 131072)
#define OFF_F1(l)  (OFF_KV(l) + 196608)
#define OFF_F2(l)  (OFF_KV(l) + 327680)
#define OFF_PROJ  (32768 + 2 * LSTRIDE)

__device__ __forceinline__ void split_pair(float a, float b, uint32_t& h, uint32_t& l) {
    __half ha = __float2half_rn(a), hb = __float2half_rn(b);
    h = (uint32_t)__half_as_ushort(ha) | ((uint32_t)__half_as_ushort(hb) << 16);
    __half la = __float2half_rn(a - __half2float(ha));
    __half lb = __float2half_rn(b - __half2float(hb));
    l = (uint32_t)__half_as_ushort(la) | ((uint32_t)__half_as_ushort(lb) << 16);
}
__device__ __forceinline__ float2 up2(uint32_t v) {
    __half2 t = *reinterpret_cast<const __half2*>(&v);
    return __half22float2(t);
}

// ---------------- wsplit_all: all weights (fp16) + BN2 prep, ONE launch -----
struct WArgs {
    const float* src[10];
    int K[10];
    int off[10];
    int row0[11];
};
__global__ void __launch_bounds__(128) wsplit_all(
    WArgs a, const float* bg, const float* bb, const float* bm, const float* bv)
{
    int blk = blockIdx.x;
    if (blk == 3456) {
        int i = threadIdx.x;
        if (i < CC) {
            float s = bg[i] * rsqrtf(bv[i] + EPS);
            g_s2[i] = s; g_b2[i] = bb[i] - bm[i] * s;
        }
        return;
    }
    int s = 0;
    while (blk >= a.row0[s + 1]) s++;
    int row = blk - a.row0[s];
    int K = a.K[s];
    const float* src = a.src[s] + (size_t)row * K;
    __half* dh = g_whi + a.off[s] + (size_t)row * K;
    for (int k = threadIdx.x; k < K; k += 128)
        dh[k] = __float2half_rn(src[k]);
}

// ---------------- dwconv3x3 + BN1 + leaky (fp32 temp) ----------------
__global__ void __launch_bounds__(256) dwconv_k(
    const float* __restrict__ x, const float* __restrict__ w,
    const float* __restrict__ bg, const float* __restrict__ bbias,
    const float* __restrict__ bm, const float* __restrict__ bv, float* __restrict__ yout)
{
    int b = blockIdx.z, c = blockIdx.y;
    int idx = blockIdx.x * 256 + threadIdx.x;
    __shared__ float ws[9]; __shared__ float sc, sh;
    if (threadIdx.x < 9) ws[threadIdx.x] = w[c * 9 + threadIdx.x];
    if (threadIdx.x == 0) {
        float s = bg[c] * rsqrtf(bv[c] + EPS);
        sc = s; sh = bbias[c] - bm[c] * s;
    }
    __syncthreads();
    int h = idx >> 6, wq = idx & 63;
    const float* xp = x + ((size_t)b * CC + c) * HWN;
    float acc = 0.f;
#pragma unroll
    for (int dh = 0; dh < 3; dh++) {
        int hh = h + dh - 1;
        if (hh < 0 || hh >= 64) continue;
#pragma unroll
        for (int dw = 0; dw < 3; dw++) {
            int w2 = wq + dw - 1;
            if (w2 < 0 || w2 >= 64) continue;
            acc = fmaf(xp[hh * 64 + w2], ws[dh * 3 + dw], acc);
        }
    }
    float o = acc * sc + sh;
    o = (o > 0.f) ? o : 0.1f * o;
    yout[((size_t)b * CC + c) * HWN + idx] = o;
}

// ---------------- y fp32 [c][pix] -> yt planes [pix][128] ----------------
__global__ void __launch_bounds__(256) ypack_k(const float* __restrict__ y)
{
    int b = blockIdx.y, tx = threadIdx.x, ty = threadIdx.y;
    int p0 = blockIdx.x * 32;
    __shared__ float sy[128][33];
    for (int ct = 0; ct < 4; ct++)
#pragma unroll
        for (int q = 0; q < 4; q++) {
            int c = ct * 32 + ty * 4 + q;
            sy[c][tx] = y[((size_t)b * CC + c) * HWN + p0 + tx];
        }
    __syncthreads();
    uint32_t wh[8], wl[8];
#pragma unroll
    for (int j = 0; j < 16; j += 2)
        split_pair(sy[ty * 16 + j][tx], sy[ty * 16 + j + 1][tx], wh[j >> 1], wl[j >> 1]);
    size_t o = ((size_t)b * HWN + p0 + tx) * CC + ty * 16;
    uint4* dh = reinterpret_cast<uint4*>(g_yth + o);
    uint4* dl = reinterpret_cast<uint4*>(g_ytl + o);
    dh[0] = make_uint4(wh[0], wh[1], wh[2], wh[3]);
    dh[1] = make_uint4(wh[4], wh[5], wh[6], wh[7]);
    dl[0] = make_uint4(wl[0], wl[1], wl[2], wl[3]);
    dl[1] = make_uint4(wl[4], wl[5], wl[6], wl[7]);
}

// ---------------- colstats + LN -> z planes [col][256] ----------------
__global__ void __launch_bounds__(256) colstats_k(
    const float* __restrict__ p,
    const float* __restrict__ lng, const float* __restrict__ lnb)
{
    int b = blockIdx.y, tx = threadIdx.x, ty = threadIdx.y;
    int col = blockIdx.x * 32 + tx;
    int lt = ty * 32 + tx;
    __shared__ float sg[256], sb[256];
    sg[lt] = lng[lt]; sb[lt] = lnb[lt];
    size_t base = (size_t)b * DD * HWN + col;
    float vals[32], s = 0.f, s2 = 0.f;
#pragma unroll
    for (int j = 0; j < 32; j++) {
        float v = p[base + ((size_t)(ty * 32 + j) << 12)];
        vals[j] = v; s += v; s2 = fmaf(v, v, s2);
    }
    __shared__ float sh1[8][32], sh2[8][32], smean[32], srstd[32];
    sh1[ty][tx] = s; sh2[ty][tx] = s2;
    __syncthreads();
    if (ty == 0) {
        float a = 0.f, a2 = 0.f;
#pragma unroll
        for (int k = 0; k < 8; k++) { a += sh1[k][tx]; a2 += sh2[k][tx]; }
        float mean = a * (1.f / DD);
        smean[tx] = mean;
        srstd[tx] = rsqrtf(a2 * (1.f / DD) - mean * mean + EPS);
    }
    __syncthreads();
    float mean = smean[tx], rstd = srstd[tx];
    uint32_t wh[16], wl[16];
#pragma unroll
    for (int j = 0; j < 32; j += 2) {
        int d = ty * 32 + j;
        float z0 = (vals[j]     - mean) * rstd * sg[d]     + sb[d];
        float z1 = (vals[j + 1] - mean) * rstd * sg[d + 1] + sb[d + 1];
        split_pair(z0, z1, wh[j >> 1], wl[j >> 1]);
    }
    size_t o = ((size_t)b * HWN + col) * DD + ty * 32;
    uint4* dh = reinterpret_cast<uint4*>(g_zth + o);
    uint4* dl = reinterpret_cast<uint4*>(g_ztl + o);
#pragma unroll
    for (int q = 0; q < 4; q++) {
        dh[q] = make_uint4(wh[4*q], wh[4*q+1], wh[4*q+2], wh[4*q+3]);
        dl[q] = make_uint4(wl[4*q], wl[4*q+1], wl[4*q+2], wl[4*q+3]);
    }
}

// ---------------- relu(v)*ctx -> z planes (reused) [n][256] ----------------
__global__ void __launch_bounds__(256) vctx_k()
{
    int b = blockIdx.y, tx = threadIdx.x, ty = threadIdx.y;
    int n0 = blockIdx.x * 32;
    int pq = n0 >> 10;
    __shared__ float sv[256][33];
    for (int dt = 0; dt < 8; dt++)
#pragma unroll
        for (int q = 0; q < 4; q++) {
            int d = dt * 32 + ty * 4 + q;
            float v = g_kv[((size_t)b * 512 + 256 + d) * HWN + n0 + tx];
            sv[d][tx] = fmaxf(v, 0.f) * g_ctx[(b << 10) + (pq << 8) + d];
        }
    __syncthreads();
    uint32_t wh[16], wl[16];
#pragma unroll
    for (int j = 0; j < 32; j += 2)
        split_pair(sv[ty * 32 + j][tx], sv[ty * 32 + j + 1][tx], wh[j >> 1], wl[j >> 1]);
    size_t o = ((size_t)b * HWN + n0 + tx) * DD + ty * 32;
    uint4* dh = reinterpret_cast<uint4*>(g_zth + o);
    uint4* dl = reinterpret_cast<uint4*>(g_ztl + o);
#pragma unroll
    for (int q = 0; q < 4; q++) {
        dh[q] = make_uint4(wh[4*q], wh[4*q+1], wh[4*q+2], wh[4*q+3]);
        dl[q] = make_uint4(wl[4*q], wl[4*q+1], wl[4*q+2], wl[4*q+3]);
    }
}

// ---------------- q-GEMV + softmax + ctx ----------------
__global__ void __launch_bounds__(256) qsoftctx_k(
    const float* __restrict__ wq, const float* __restrict__ qb)
{
    __shared__ float sprob[1024], wqs[256], red[256];
    int tid = threadIdx.x;
    int b = blockIdx.x >> 2, pq = blockIdx.x & 3;
    wqs[tid] = wq[tid];
    __syncthreads();
    float q0 = qb[0], qv[4];
#pragma unroll
    for (int r = 0; r < 4; r++) {
        int n = tid + (r << 8);
        size_t base = ((size_t)b * HWN + pq * 1024 + n) * DD;
        const uint4* zh = reinterpret_cast<const uint4*>(g_zth + base);
        const uint4* zl = reinterpret_cast<const uint4*>(g_ztl + base);
        float acc = q0;
#pragma unroll 4
        for (int i = 0; i < 32; i++) {
            uint4 H = zh[i], L = zl[i];
            const float* w8 = wqs + i * 8;
            float2 h0 = up2(H.x), l0 = up2(L.x), h1 = up2(H.y), l1 = up2(L.y);
            float2 h2 = up2(H.z), l2 = up2(L.z), h3 = up2(H.w), l3 = up2(L.w);
            acc = fmaf(w8[0], h0.x + l0.x, acc); acc = fmaf(w8[1], h0.y + l0.y, acc);
            acc = fmaf(w8[2], h1.x + l1.x, acc); acc = fmaf(w8[3], h1.y + l1.y, acc);
            acc = fmaf(w8[4], h2.x + l2.x, acc); acc = fmaf(w8[5], h2.y + l2.y, acc);
            acc = fmaf(w8[6], h3.x + l3.x, acc); acc = fmaf(w8[7], h3.y + l3.y, acc);
        }
        qv[r] = acc;
    }
    float lm = fmaxf(fmaxf(qv[0], qv[1]), fmaxf(qv[2], qv[3]));
    red[tid] = lm; __syncthreads();
    for (int s = 128; s > 0; s >>= 1) { if (tid < s) red[tid] = fmaxf(red[tid], red[tid+s]); __syncthreads(); }
    float gm = red[0]; __syncthreads();
    float e[4], ls = 0.f;
#pragma unroll
    for (int r = 0; r < 4; r++) { e[r] = __expf(qv[r] - gm); ls += e[r]; }
    red[tid] = ls; __syncthreads();
    for (int s = 128; s > 0; s >>= 1) { if (tid < s) red[tid] += red[tid+s]; __syncthreads(); }
    float inv = 1.f / red[0];
#pragma unroll
    for (int r = 0; r < 4; r++) sprob[tid + (r << 8)] = e[r] * inv;
    __syncthreads();
    int warp = tid >> 5, lane = tid & 31;
    for (int d = warp; d < 256; d += 8) {
        const float* kr = g_kv + ((size_t)b * 512 + d) * HWN + pq * 1024;
        float acc = 0.f;
#pragma unroll 8
        for (int n = lane; n < 1024; n += 32) acc = fmaf(kr[n], sprob[n], acc);
#pragma unroll
        for (int o = 16; o > 0; o >>= 1) acc += __shfl_down_sync(0xffffffffu, acc, o);
        if (lane == 0) g_ctx[(b << 10) + (pq << 8) + d] = acc;
    }
}

// ============================================================================
// fp16 GEMM v14: W single-plane; B hi/lo (NPL=2) or single-plane (NPL=1)
// 512 threads, 16 warps of 32x32, CTA 128x128, k-tile 32, cp.async 3-stage
// smem stage 24KB: A 8K | Bh 8K | Bl 8K (Bl slot unused when NPL=1)
// ============================================================================
__device__ __forceinline__ uint32_t smem_u32(const void* p) {
    uint32_t a;
    asm("{ .reg .u64 t; cvta.to.shared.u64 t, %1; cvt.u32.u64 %0, t; }" : "=r"(a) : "l"(p));
    return a;
}
#define LDSM4(R, A)                                                            \
    asm volatile("ldmatrix.sync.aligned.m8n8.x4.shared.b16 {%0,%1,%2,%3}, [%4];" \
        : "=r"((R)[0]), "=r"((R)[1]), "=r"((R)[2]), "=r"((R)[3]) : "r"(A))
#define HMMA32(D, A, B0, B1)                                                   \
    asm volatile("mma.sync.aligned.m16n8k16.row.col.f32.f16.f16.f32 "          \
        "{%0,%1,%2,%3},{%4,%5,%6,%7},{%8,%9},{%0,%1,%2,%3};"                   \
        : "+f"((D)[0]), "+f"((D)[1]), "+f"((D)[2]), "+f"((D)[3])               \
        : "r"((A)[0]), "r"((A)[1]), "r"((A)[2]), "r"((A)[3]), "r"(B0), "r"(B1))
#define CPA(D, S) asm volatile("cp.async.cg.shared.global [%0], [%1], 16;" :: "r"(D), "l"(S))

enum { E_KV = 0, E_RESID = 1, E_PERM_P = 2, E_OUT = 3, E_H = 4 };
#define G14_SMEM 73728   // 3 stages x 24KB

__device__ __forceinline__ uint32_t swz(int r, int c) {
    return (uint32_t)(r * 64 + ((c ^ ((r >> 1) & 3)) << 4));
}

template<int EP, int NPL>
__global__ void __launch_bounds__(512, 2) gemm14(
    int woff, const __half* __restrict__ Bhp, const __half* __restrict__ Blp,
    float* __restrict__ Y, const float* __restrict__ bias, int M, int K)
{
    extern __shared__ __align__(16) char smc[];
    const uint32_t sma = smem_u32(smc);
    const int tid = threadIdx.x, wid = tid >> 5, lane = tid & 31;
    const int gid = lane >> 2, tig = lane & 3;
    const int b = blockIdx.z, colT = blockIdx.x << 7, rowT = blockIdx.y << 7;
    const int mw = (wid & 3) << 5, nw = (wid >> 2) << 5;
    const int nT = K >> 5;

    const __half* gAh = g_whi + woff;

    float acc[2][4][4];
#pragma unroll
    for (int i = 0; i < 2; i++)
#pragma unroll
        for (int j = 0; j < 4; j++)
#pragma unroll
            for (int k = 0; k < 4; k++) acc[i][j][k] = 0.f;

    const int pr = tid >> 2, pc = tid & 3;

    auto issue = [&](int c) {
        uint32_t base = sma + (c % 3) * 24576;
        int k0 = c << 5;
        uint32_t sw = swz(pr, pc);
        size_t ga = (size_t)(rowT + pr) * K + k0 + pc * 8;
        size_t gb = ((size_t)b * HWN + colT + pr) * K + k0 + pc * 8;
        CPA(base + sw,        gAh + ga);
        CPA(base + 8192 + sw, Bhp + gb);
        if (NPL == 2) CPA(base + 16384 + sw, Blp + gb);
        asm volatile("cp.async.commit_group;");
    };

    issue(0);
    if (nT > 1) issue(1);
    for (int c = 0; c < nT; c++) {
        if (c + 1 < nT) asm volatile("cp.async.wait_group 1;");
        else            asm volatile("cp.async.wait_group 0;");
        __syncthreads();
        if (c + 2 < nT) issue(c + 2);
        uint32_t sb = sma + (c % 3) * 24576;
#pragma unroll
        for (int h = 0; h < 2; h++) {
            int cc = h * 2 + (lane >> 4);
            uint32_t Ah[2][4];
#pragma unroll
            for (int mi = 0; mi < 2; mi++) {
                int r = mw + mi * 16 + (lane & 15);
                LDSM4(Ah[mi], sb + swz(r, cc));
            }
#pragma unroll
            for (int p = 0; p < 2; p++) {
                uint32_t Bh[4], Bl[4];
                int r = nw + p * 16 + (lane & 15);
                uint32_t ad = sb + 8192 + swz(r, cc);
                LDSM4(Bh, ad);
                if (NPL == 2) LDSM4(Bl, ad + 8192);
#pragma unroll
                for (int mi = 0; mi < 2; mi++)
#pragma unroll
                    for (int q = 0; q < 2; q++) {
                        int ni = p * 2 + q;
                        HMMA32(acc[mi][ni], Ah[mi], Bh[q], Bh[q + 2]);
                        if (NPL == 2) HMMA32(acc[mi][ni], Ah[mi], Bl[q], Bl[q + 2]);
                    }
            }
        }
    }

    // ---- epilogue ----
    if (EP == E_H) {
        // leaky + fp16 (single plane), smem transpose -> g_hth [col][FF_]
        __syncthreads();
        __half* trh = reinterpret_cast<__half*>(smc);
#pragma unroll
        for (int mi = 0; mi < 2; mi++) {
            float bi0 = bias[rowT + mw + mi * 16 + gid];
            float bi1 = bias[rowT + mw + mi * 16 + gid + 8];
#pragma unroll
            for (int ni = 0; ni < 4; ni++)
#pragma unroll
                for (int r = 0; r < 4; r++) {
                    float v = acc[mi][ni][r] + ((r >> 1) ? bi1 : bi0);
                    v = (v > 0.f) ? v : 0.1f * v;
                    int ml = mw + mi * 16 + gid + (r >> 1) * 8;
                    int nl = nw + ni * 8 + tig * 2 + (r & 1);
                    trh[nl * 136 + ml] = __float2half_rn(v);
                }
        }
        __syncthreads();
        int nl = tid >> 2, qt = tid & 3;
        const uint4* s1 = reinterpret_cast<const uint4*>(trh + nl * 136 + qt * 32);
        size_t o = ((size_t)b * HWN + colT + nl) * FF_ + rowT + qt * 32;
        uint4* d1 = reinterpret_cast<uint4*>(g_hth + o);
#pragma unroll
        for (int j = 0; j < 4; j++) d1[j] = s1[j];
        return;
    }

#pragma unroll
    for (int mi = 0; mi < 2; mi++)
#pragma unroll
        for (int r2 = 0; r2 < 2; r2++) {
            int m = rowT + mw + mi * 16 + gid + r2 * 8;
            float bi = (EP == E_OUT) ? 0.f : bias[m];
#pragma unroll
            for (int ni = 0; ni < 4; ni++) {
                int c0 = colT + nw + ni * 8 + tig * 2;
                float v0 = acc[mi][ni][r2 * 2 + 0] + bi;
                float v1 = acc[mi][ni][r2 * 2 + 1] + bi;
                if (EP == E_OUT) {
                    float rs = g_s2[m], rb = g_b2[m];
                    v0 = v0 * rs + rb; v1 = v1 * rs + rb;
                    float* yb = Y + ((size_t)b * CC + m) * HWN;
#pragma unroll
                    for (int cb = 0; cb < 2; cb++) {
                        int col = c0 + cb;
                        int pq = col >> 10, n = col & 1023;
                        int h = ((n >> 5) << 1) | (pq >> 1);
                        int w2 = ((n & 31) << 1) | (pq & 1);
                        yb[h * 64 + w2] = cb ? v1 : v0;
                    }
                } else if (EP == E_PERM_P) {
#pragma unroll
                    for (int cb = 0; cb < 2; cb++) {
                        int col = c0 + cb;
                        int h = col >> 6, w = col & 63;
                        int pc2 = ((((h & 1) << 1) | (w & 1)) << 10) | ((h >> 1) << 5) | (w >> 1);
                        Y[((size_t)b * M + m) * HWN + pc2] = cb ? v1 : v0;
                    }
                } else {
                    float2* yp = reinterpret_cast<float2*>(&Y[((size_t)b * M + m) * HWN + c0]);
                    if (EP == E_RESID) {
                        float2 o = *yp;
                        o.x += v0; o.y += v1;
                        *yp = o;
                    } else {
                        *yp = make_float2(v0, v1);
                    }
                }
            }
        }
}

// ---------------- host ----------------
template<int EP, int NPL>
static void launch14(int woff, const __half* Bh, const __half* Bl,
                     float* Y, const float* bias, int M, int K)
{
    cudaFuncSetAttribute(gemm14<EP, NPL>, cudaFuncAttributeMaxDynamicSharedMemorySize, G14_SMEM);
    gemm14<EP, NPL><<<dim3(32, M / 128, BB), 512, G14_SMEM>>>(woff, Bh, Bl, Y, bias, M, K);
}

extern "C" void kernel_launch(void* const* d_in, const int* in_sizes, int n_in,
                              void* d_out, int out_size)
{
    const float* x     = (const float*)d_in[0];
    const float* dw_w  = (const float*)d_in[1];
    const float* bn1_g = (const float*)d_in[2];
    const float* bn1_b = (const float*)d_in[3];
    const float* bn1_m = (const float*)d_in[4];
    const float* bn1_v = (const float*)d_in[5];
    const float* c1_w  = (const float*)d_in[6];
    const float* c1_b  = (const float*)d_in[7];
    const float* ln1_g = (const float*)d_in[8];
    const float* ln1_b = (const float*)d_in[9];
    const float* qkv_w = (const float*)d_in[10];
    const float* qkv_b = (const float*)d_in[11];
    const float* out_w = (const float*)d_in[12];
    const float* out_b = (const float*)d_in[13];
    const float* ln2_g = (const float*)d_in[14];
    const float* ln2_b = (const float*)d_in[15];
    const float* f1_w  = (const float*)d_in[16];
    const float* f1_b  = (const float*)d_in[17];
    const float* f2_w  = (const float*)d_in[18];
    const float* f2_b  = (const float*)d_in[19];
    const float* lnf_g = (const float*)d_in[20];
    const float* lnf_b = (const float*)d_in[21];
    const float* projw = (const float*)d_in[22];
    const float* bn2_g = (const float*)d_in[23];
    const float* bn2_b = (const float*)d_in[24];
    const float* bn2_m = (const float*)d_in[25];
    const float* bn2_v = (const float*)d_in[26];
    float* out = (float*)d_out;

    void* vp;
    cudaGetSymbolAddress(&vp, g_p);   float* p  = (float*)vp;
    cudaGetSymbolAddress(&vp, g_kv);  float* kv = (float*)vp;
    cudaGetSymbolAddress(&vp, g_zth); __half* zth = (__half*)vp;
    cudaGetSymbolAddress(&vp, g_ztl); __half* ztl = (__half*)vp;
    cudaGetSymbolAddress(&vp, g_hth); __half* hth = (__half*)vp;
    cudaGetSymbolAddress(&vp, g_yth); __half* yth = (__half*)vp;
    cudaGetSymbolAddress(&vp, g_ytl); __half* ytl = (__half*)vp;

    // single weight-convert launch (also folds BN2)
    WArgs wa;
    const float* qw0 = qkv_w;
    const float* qw1 = qkv_w + (size_t)513 * DD;
    const float* srcs[10] = {
        c1_w,
        qw0 + DD, out_w, f1_w, f2_w,
        qw1 + DD, out_w + (size_t)DD * DD, f1_w + (size_t)FF_ * DD, f2_w + (size_t)DD * FF_,
        projw };
    int Ks[10]   = {128, 256, 256, 256, 512, 256, 256, 256, 512, 256};
    int offs[10] = {OFF_C1, OFF_KV(0), OFF_OUT(0), OFF_F1(0), OFF_F2(0),
                    OFF_KV(1), OFF_OUT(1), OFF_F1(1), OFF_F2(1), OFF_PROJ};
    int rows[10] = {256, 512, 256, 512, 256, 512, 256, 512, 256, 128};
    int acc = 0;
    for (int i = 0; i < 10; i++) {
        wa.src[i] = srcs[i]; wa.K[i] = Ks[i]; wa.off[i] = offs[i];
        wa.row0[i] = acc; acc += rows[i];
    }
    wa.row0[10] = acc;  // 3456
    wsplit_all<<<3457, 128>>>(wa, bn2_g, bn2_b, bn2_m, bn2_v);

    dwconv_k<<<dim3(16, CC, BB), 256>>>(x, dw_w, bn1_g, bn1_b, bn1_m, bn1_v, kv);
    ypack_k<<<dim3(128, BB), dim3(32, 8)>>>(kv);

    // c1: p = patchify(W_c1 @ y + b)
    launch14<E_PERM_P, 2>(OFF_C1, yth, ytl, p, c1_b, DD, 128);

    for (int l = 0; l < 2; l++) {
        const float* qw  = qkv_w + (size_t)l * 513 * DD;
        const float* qbi = qkv_b + l * 513;

        colstats_k<<<dim3(128, BB), dim3(32, 8)>>>(p, ln1_g + l * DD, ln1_b + l * DD);
        launch14<E_KV, 2>(OFF_KV(l), zth, ztl, kv, qbi + 1, 512, 256);
        qsoftctx_k<<<128, 256>>>(qw, qbi);
        vctx_k<<<dim3(128, BB), dim3(32, 8)>>>();
        launch14<E_RESID, 2>(OFF_OUT(l), zth, ztl, p, out_b + l * DD, DD, 256);

        colstats_k<<<dim3(128, BB), dim3(32, 8)>>>(p, ln2_g + l * DD, ln2_b + l * DD);
        launch14<E_H, 2>(OFF_F1(l), zth, ztl, nullptr, f1_b + l * FF_, FF_, 256);
        // f2 reads single-plane h
        launch14<E_RESID, 1>(OFF_F2(l), hth, nullptr, p, f2_b + l * DD, DD, 512);
    }

    colstats_k<<<dim3(128, BB), dim3(32, 8)>>>(p, lnf_g, lnf_b);
    launch14<E_OUT, 2>(OFF_PROJ, zth, ztl, out, nullptr, CC, 256);
}

// round 15
// speedup vs baseline: 1.3771x; 1.1270x over previous
#include <cuda_runtime.h>
#include <cuda_fp16.h>
#include <cstdint>

#define BB   32
#define CC   128
#define DD   256
#define FF_  512
#define HWN  4096
#define EPS  1e-5f

// ---------------- scratch ----------------
__device__ float g_p  [(size_t)BB * DD  * HWN];    // token tensor fp32
__device__ float g_kv [(size_t)BB * 512 * HWN];    // k|v fp32 (also dwconv temp)
__device__ float g_ctx[BB * 4 * DD];
__device__ float g_s2[CC], g_b2[CC];

// transposed fp16 hi/lo activation planes, [b][col][k]
__device__ __half g_zth[(size_t)BB * HWN * DD ];
__device__ __half g_ztl[(size_t)BB * HWN * DD ];
__device__ __half g_hth[(size_t)BB * HWN * FF_];   // h: single plane
__device__ __half g_yth[(size_t)BB * HWN * CC ];
__device__ __half g_ytl[(size_t)BB * HWN * CC ];

#define WTOT 983040
__device__ __half g_whi[WTOT];          // single-plane fp16 weights
#define OFF_C1    0
#define LSTRIDE   458752
#define OFF_KV(l)  (32768 + (l) * LSTRIDE)
#define OFF_OUT(l) (OFF_KV(l) + 131072)
#define OFF_F1(l)  (OFF_KV(l) + 196608)
#define OFF_F2(l)  (OFF_KV(l) + 327680)
#define OFF_PROJ  (32768 + 2 * LSTRIDE)

__device__ __forceinline__ void split_pair(float a, float b, uint32_t& h, uint32_t& l) {
    __half ha = __float2half_rn(a), hb = __float2half_rn(b);
    h = (uint32_t)__half_as_ushort(ha) | ((uint32_t)__half_as_ushort(hb) << 16);
    __half la = __float2half_rn(a - __half2float(ha));
    __half lb = __float2half_rn(b - __half2float(hb));
    l = (uint32_t)__half_as_ushort(la) | ((uint32_t)__half_as_ushort(lb) << 16);
}
__device__ __forceinline__ uint32_t pack_hi(float a, float b) {
    __half ha = __float2half_rn(a), hb = __float2half_rn(b);
    return (uint32_t)__half_as_ushort(ha) | ((uint32_t)__half_as_ushort(hb) << 16);
}
__device__ __forceinline__ float2 up2(uint32_t v) {
    __half2 t = *reinterpret_cast<const __half2*>(&v);
    return __half22float2(t);
}

// ---------------- wsplit_all: all weights (fp16) + BN2 prep, ONE launch -----
struct WArgs {
    const float* src[10];
    int K[10];
    int off[10];
    int row0[11];
};
__global__ void __launch_bounds__(128) wsplit_all(
    WArgs a, const float* bg, const float* bb, const float* bm, const float* bv)
{
    int blk = blockIdx.x;
    if (blk == 3456) {
        int i = threadIdx.x;
        if (i < CC) {
            float s = bg[i] * rsqrtf(bv[i] + EPS);
            g_s2[i] = s; g_b2[i] = bb[i] - bm[i] * s;
        }
        return;
    }
    int s = 0;
    while (blk >= a.row0[s + 1]) s++;
    int row = blk - a.row0[s];
    int K = a.K[s];
    const float* src = a.src[s] + (size_t)row * K;
    __half* dh = g_whi + a.off[s] + (size_t)row * K;
    for (int k = threadIdx.x; k < K; k += 128)
        dh[k] = __float2half_rn(src[k]);
}

// ---------------- dwconv3x3 + BN1 + leaky (fp32 temp) ----------------
__global__ void __launch_bounds__(256) dwconv_k(
    const float* __restrict__ x, const float* __restrict__ w,
    const float* __restrict__ bg, const float* __restrict__ bbias,
    const float* __restrict__ bm, const float* __restrict__ bv, float* __restrict__ yout)
{
    int b = blockIdx.z, c = blockIdx.y;
    int idx = blockIdx.x * 256 + threadIdx.x;
    __shared__ float ws[9]; __shared__ float sc, sh;
    if (threadIdx.x < 9) ws[threadIdx.x] = w[c * 9 + threadIdx.x];
    if (threadIdx.x == 0) {
        float s = bg[c] * rsqrtf(bv[c] + EPS);
        sc = s; sh = bbias[c] - bm[c] * s;
    }
    __syncthreads();
    int h = idx >> 6, wq = idx & 63;
    const float* xp = x + ((size_t)b * CC + c) * HWN;
    float acc = 0.f;
#pragma unroll
    for (int dh = 0; dh < 3; dh++) {
        int hh = h + dh - 1;
        if (hh < 0 || hh >= 64) continue;
#pragma unroll
        for (int dw = 0; dw < 3; dw++) {
            int w2 = wq + dw - 1;
            if (w2 < 0 || w2 >= 64) continue;
            acc = fmaf(xp[hh * 64 + w2], ws[dh * 3 + dw], acc);
        }
    }
    float o = acc * sc + sh;
    o = (o > 0.f) ? o : 0.1f * o;
    yout[((size_t)b * CC + c) * HWN + idx] = o;
}

// ---------------- y fp32 [c][pix] -> yt planes [pix][128] ----------------
__global__ void __launch_bounds__(256) ypack_k(const float* __restrict__ y)
{
    int b = blockIdx.y, tx = threadIdx.x, ty = threadIdx.y;
    int p0 = blockIdx.x * 32;
    __shared__ float sy[128][33];
    for (int ct = 0; ct < 4; ct++)
#pragma unroll
        for (int q = 0; q < 4; q++) {
            int c = ct * 32 + ty * 4 + q;
            sy[c][tx] = y[((size_t)b * CC + c) * HWN + p0 + tx];
        }
    __syncthreads();
    uint32_t wh[8], wl[8];
#pragma unroll
    for (int j = 0; j < 16; j += 2)
        split_pair(sy[ty * 16 + j][tx], sy[ty * 16 + j + 1][tx], wh[j >> 1], wl[j >> 1]);
    size_t o = ((size_t)b * HWN + p0 + tx) * CC + ty * 16;
    uint4* dh = reinterpret_cast<uint4*>(g_yth + o);
    uint4* dl = reinterpret_cast<uint4*>(g_ytl + o);
    dh[0] = make_uint4(wh[0], wh[1], wh[2], wh[3]);
    dh[1] = make_uint4(wh[4], wh[5], wh[6], wh[7]);
    dl[0] = make_uint4(wl[0], wl[1], wl[2], wl[3]);
    dl[1] = make_uint4(wl[4], wl[5], wl[6], wl[7]);
}

// ---------------- colstats + LN -> z planes [col][256] ----------------
__global__ void __launch_bounds__(256) colstats_k(
    const float* __restrict__ p,
    const float* __restrict__ lng, const float* __restrict__ lnb)
{
    int b = blockIdx.y, tx = threadIdx.x, ty = threadIdx.y;
    int col = blockIdx.x * 32 + tx;
    int lt = ty * 32 + tx;
    __shared__ float sg[256], sb[256];
    sg[lt] = lng[lt]; sb[lt] = lnb[lt];
    size_t base = (size_t)b * DD * HWN + col;
    float vals[32], s = 0.f, s2 = 0.f;
#pragma unroll
    for (int j = 0; j < 32; j++) {
        float v = p[base + ((size_t)(ty * 32 + j) << 12)];
        vals[j] = v; s += v; s2 = fmaf(v, v, s2);
    }
    __shared__ float sh1[8][32], sh2[8][32], smean[32], srstd[32];
    sh1[ty][tx] = s; sh2[ty][tx] = s2;
    __syncthreads();
    if (ty == 0) {
        float a = 0.f, a2 = 0.f;
#pragma unroll
        for (int k = 0; k < 8; k++) { a += sh1[k][tx]; a2 += sh2[k][tx]; }
        float mean = a * (1.f / DD);
        smean[tx] = mean;
        srstd[tx] = rsqrtf(a2 * (1.f / DD) - mean * mean + EPS);
    }
    __syncthreads();
    float mean = smean[tx], rstd = srstd[tx];
    uint32_t wh[16], wl[16];
#pragma unroll
    for (int j = 0; j < 32; j += 2) {
        int d = ty * 32 + j;
        float z0 = (vals[j]     - mean) * rstd * sg[d]     + sb[d];
        float z1 = (vals[j + 1] - mean) * rstd * sg[d + 1] + sb[d + 1];
        split_pair(z0, z1, wh[j >> 1], wl[j >> 1]);
    }
    size_t o = ((size_t)b * HWN + col) * DD + ty * 32;
    uint4* dh = reinterpret_cast<uint4*>(g_zth + o);
    uint4* dl = reinterpret_cast<uint4*>(g_ztl + o);
#pragma unroll
    for (int q = 0; q < 4; q++) {
        dh[q] = make_uint4(wh[4*q], wh[4*q+1], wh[4*q+2], wh[4*q+3]);
        dl[q] = make_uint4(wl[4*q], wl[4*q+1], wl[4*q+2], wl[4*q+3]);
    }
}

// ---------------- relu(v)*ctx -> z hi plane only [n][256] ----------------
__global__ void __launch_bounds__(256) vctx_k()
{
    int b = blockIdx.y, tx = threadIdx.x, ty = threadIdx.y;
    int n0 = blockIdx.x * 32;
    int pq = n0 >> 10;
    __shared__ float sv[256][33];
    for (int dt = 0; dt < 8; dt++)
#pragma unroll
        for (int q = 0; q < 4; q++) {
            int d = dt * 32 + ty * 4 + q;
            float v = g_kv[((size_t)b * 512 + 256 + d) * HWN + n0 + tx];
            sv[d][tx] = fmaxf(v, 0.f) * g_ctx[(b << 10) + (pq << 8) + d];
        }
    __syncthreads();
    uint32_t wh[16];
#pragma unroll
    for (int j = 0; j < 32; j += 2)
        wh[j >> 1] = pack_hi(sv[ty * 32 + j][tx], sv[ty * 32 + j + 1][tx]);
    size_t o = ((size_t)b * HWN + n0 + tx) * DD + ty * 32;
    uint4* dh = reinterpret_cast<uint4*>(g_zth + o);
#pragma unroll
    for (int q = 0; q < 4; q++)
        dh[q] = make_uint4(wh[4*q], wh[4*q+1], wh[4*q+2], wh[4*q+3]);
}

// ---------------- q-GEMV + softmax + ctx ----------------
__global__ void __launch_bounds__(256) qsoftctx_k(
    const float* __restrict__ wq, const float* __restrict__ qb)
{
    __shared__ float sprob[1024], wqs[256], red[256];
    int tid = threadIdx.x;
    int b = blockIdx.x >> 2, pq = blockIdx.x & 3;
    wqs[tid] = wq[tid];
    __syncthreads();
    float q0 = qb[0], qv[4];
#pragma unroll
    for (int r = 0; r < 4; r++) {
        int n = tid + (r << 8);
        size_t base = ((size_t)b * HWN + pq * 1024 + n) * DD;
        const uint4* zh = reinterpret_cast<const uint4*>(g_zth + base);
        const uint4* zl = reinterpret_cast<const uint4*>(g_ztl + base);
        float acc = q0;
#pragma unroll 4
        for (int i = 0; i < 32; i++) {
            uint4 H = zh[i], L = zl[i];
            const float* w8 = wqs + i * 8;
            float2 h0 = up2(H.x), l0 = up2(L.x), h1 = up2(H.y), l1 = up2(L.y);
            float2 h2 = up2(H.z), l2 = up2(L.z), h3 = up2(H.w), l3 = up2(L.w);
            acc = fmaf(w8[0], h0.x + l0.x, acc); acc = fmaf(w8[1], h0.y + l0.y, acc);
            acc = fmaf(w8[2], h1.x + l1.x, acc); acc = fmaf(w8[3], h1.y + l1.y, acc);
            acc = fmaf(w8[4], h2.x + l2.x, acc); acc = fmaf(w8[5], h2.y + l2.y, acc);
            acc = fmaf(w8[6], h3.x + l3.x, acc); acc = fmaf(w8[7], h3.y + l3.y, acc);
        }
        qv[r] = acc;
    }
    float lm = fmaxf(fmaxf(qv[0], qv[1]), fmaxf(qv[2], qv[3]));
    red[tid] = lm; __syncthreads();
    for (int s = 128; s > 0; s >>= 1) { if (tid < s) red[tid] = fmaxf(red[tid], red[tid+s]); __syncthreads(); }
    float gm = red[0]; __syncthreads();
    float e[4], ls = 0.f;
#pragma unroll
    for (int r = 0; r < 4; r++) { e[r] = __expf(qv[r] - gm); ls += e[r]; }
    red[tid] = ls; __syncthreads();
    for (int s = 128; s > 0; s >>= 1) { if (tid < s) red[tid] += red[tid+s]; __syncthreads(); }
    float inv = 1.f / red[0];
#pragma unroll
    for (int r = 0; r < 4; r++) sprob[tid + (r << 8)] = e[r] * inv;
    __syncthreads();
    int warp = tid >> 5, lane = tid & 31;
    for (int d = warp; d < 256; d += 8) {
        const float* kr = g_kv + ((size_t)b * 512 + d) * HWN + pq * 1024;
        float acc = 0.f;
#pragma unroll 8
        for (int n = lane; n < 1024; n += 32) acc = fmaf(kr[n], sprob[n], acc);
#pragma unroll
        for (int o = 16; o > 0; o >>= 1) acc += __shfl_down_sync(0xffffffffu, acc, o);
        if (lane == 0) g_ctx[(b << 10) + (pq << 8) + d] = acc;
    }
}

// ============================================================================
// fp16 GEMM v15: W single-plane; B hi/lo (NPL=2) or single-plane (NPL=1)
// 512 threads, 16 warps of 32x32, CTA 128x128, k-tile 32, cp.async 3-stage
// smem stage 24KB: A 8K | Bh 8K | Bl 8K (Bl slot unused when NPL=1)
// ============================================================================
__device__ __forceinline__ uint32_t smem_u32(const void* p) {
    uint32_t a;
    asm("{ .reg .u64 t; cvta.to.shared.u64 t, %1; cvt.u32.u64 %0, t; }" : "=r"(a) : "l"(p));
    return a;
}
#define LDSM4(R, A)                                                            \
    asm volatile("ldmatrix.sync.aligned.m8n8.x4.shared.b16 {%0,%1,%2,%3}, [%4];" \
        : "=r"((R)[0]), "=r"((R)[1]), "=r"((R)[2]), "=r"((R)[3]) : "r"(A))
#define HMMA32(D, A, B0, B1)                                                   \
    asm volatile("mma.sync.aligned.m16n8k16.row.col.f32.f16.f16.f32 "          \
        "{%0,%1,%2,%3},{%4,%5,%6,%7},{%8,%9},{%0,%1,%2,%3};"                   \
        : "+f"((D)[0]), "+f"((D)[1]), "+f"((D)[2]), "+f"((D)[3])               \
        : "r"((A)[0]), "r"((A)[1]), "r"((A)[2]), "r"((A)[3]), "r"(B0), "r"(B1))
#define CPA(D, S) asm volatile("cp.async.cg.shared.global [%0], [%1], 16;" :: "r"(D), "l"(S))

enum { E_KV = 0, E_RESID = 1, E_PERM_P = 2, E_OUT = 3, E_H = 4 };
#define G15_SMEM 73728   // 3 stages x 24KB

__device__ __forceinline__ uint32_t swz(int r, int c) {
    return (uint32_t)(r * 64 + ((c ^ ((r >> 1) & 3)) << 4));
}

template<int EP, int NPL>
__global__ void __launch_bounds__(512, 2) gemm15(
    int woff, const __half* __restrict__ Bhp, const __half* __restrict__ Blp,
    float* __restrict__ Y, const float* __restrict__ bias, int M, int K)
{
    extern __shared__ __align__(16) char smc[];
    const uint32_t sma = smem_u32(smc);
    const int tid = threadIdx.x, wid = tid >> 5, lane = tid & 31;
    const int gid = lane >> 2, tig = lane & 3;
    const int b = blockIdx.z, colT = blockIdx.x << 7, rowT = blockIdx.y << 7;
    const int mw = (wid & 3) << 5, nw = (wid >> 2) << 5;
    const int nT = K >> 5;

    const __half* gAh = g_whi + woff;

    float acc[2][4][4];
#pragma unroll
    for (int i = 0; i < 2; i++)
#pragma unroll
        for (int j = 0; j < 4; j++)
#pragma unroll
            for (int k = 0; k < 4; k++) acc[i][j][k] = 0.f;

    const int pr = tid >> 2, pc = tid & 3;

    auto issue = [&](int c) {
        uint32_t base = sma + (c % 3) * 24576;
        int k0 = c << 5;
        uint32_t sw = swz(pr, pc);
        size_t ga = (size_t)(rowT + pr) * K + k0 + pc * 8;
        size_t gb = ((size_t)b * HWN + colT + pr) * K + k0 + pc * 8;
        CPA(base + sw,        gAh + ga);
        CPA(base + 8192 + sw, Bhp + gb);
        if (NPL == 2) CPA(base + 16384 + sw, Blp + gb);
        asm volatile("cp.async.commit_group;");
    };

    issue(0);
    if (nT > 1) issue(1);
    for (int c = 0; c < nT; c++) {
        if (c + 1 < nT) asm volatile("cp.async.wait_group 1;");
        else            asm volatile("cp.async.wait_group 0;");
        __syncthreads();
        if (c + 2 < nT) issue(c + 2);
        uint32_t sb = sma + (c % 3) * 24576;
#pragma unroll
        for (int h = 0; h < 2; h++) {
            int cc = h * 2 + (lane >> 4);
            uint32_t Ah[2][4];
#pragma unroll
            for (int mi = 0; mi < 2; mi++) {
                int r = mw + mi * 16 + (lane & 15);
                LDSM4(Ah[mi], sb + swz(r, cc));
            }
#pragma unroll
            for (int p = 0; p < 2; p++) {
                uint32_t Bh[4], Bl[4];
                int r = nw + p * 16 + (lane & 15);
                uint32_t ad = sb + 8192 + swz(r, cc);
                LDSM4(Bh, ad);
                if (NPL == 2) LDSM4(Bl, ad + 8192);
#pragma unroll
                for (int mi = 0; mi < 2; mi++)
#pragma unroll
                    for (int q = 0; q < 2; q++) {
                        int ni = p * 2 + q;
                        HMMA32(acc[mi][ni], Ah[mi], Bh[q], Bh[q + 2]);
                        if (NPL == 2) HMMA32(acc[mi][ni], Ah[mi], Bl[q], Bl[q + 2]);
                    }
            }
        }
    }

    // ---- epilogue ----
    if (EP == E_H) {
        // leaky + fp16 (single plane), smem transpose -> g_hth [col][FF_]
        __syncthreads();
        __half* trh = reinterpret_cast<__half*>(smc);
#pragma unroll
        for (int mi = 0; mi < 2; mi++) {
            float bi0 = bias[rowT + mw + mi * 16 + gid];
            float bi1 = bias[rowT + mw + mi * 16 + gid + 8];
#pragma unroll
            for (int ni = 0; ni < 4; ni++)
#pragma unroll
                for (int r = 0; r < 4; r++) {
                    float v = acc[mi][ni][r] + ((r >> 1) ? bi1 : bi0);
                    v = (v > 0.f) ? v : 0.1f * v;
                    int ml = mw + mi * 16 + gid + (r >> 1) * 8;
                    int nl = nw + ni * 8 + tig * 2 + (r & 1);
                    trh[nl * 136 + ml] = __float2half_rn(v);
                }
        }
        __syncthreads();
        int nl = tid >> 2, qt = tid & 3;
        const uint4* s1 = reinterpret_cast<const uint4*>(trh + nl * 136 + qt * 32);
        size_t o = ((size_t)b * HWN + colT + nl) * FF_ + rowT + qt * 32;
        uint4* d1 = reinterpret_cast<uint4*>(g_hth + o);
#pragma unroll
        for (int j = 0; j < 4; j++) d1[j] = s1[j];
        return;
    }

#pragma unroll
    for (int mi = 0; mi < 2; mi++)
#pragma unroll
        for (int r2 = 0; r2 < 2; r2++) {
            int m = rowT + mw + mi * 16 + gid + r2 * 8;
            float bi = (EP == E_OUT) ? 0.f : bias[m];
#pragma unroll
            for (int ni = 0; ni < 4; ni++) {
                int c0 = colT + nw + ni * 8 + tig * 2;
                float v0 = acc[mi][ni][r2 * 2 + 0] + bi;
                float v1 = acc[mi][ni][r2 * 2 + 1] + bi;
                if (EP == E_OUT) {
                    float rs = g_s2[m], rb = g_b2[m];
                    v0 = v0 * rs + rb; v1 = v1 * rs + rb;
                    float* yb = Y + ((size_t)b * CC + m) * HWN;
#pragma unroll
                    for (int cb = 0; cb < 2; cb++) {
                        int col = c0 + cb;
                        int pq = col >> 10, n = col & 1023;
                        int h = ((n >> 5) << 1) | (pq >> 1);
                        int w2 = ((n & 31) << 1) | (pq & 1);
                        yb[h * 64 + w2] = cb ? v1 : v0;
                    }
                } else if (EP == E_PERM_P) {
#pragma unroll
                    for (int cb = 0; cb < 2; cb++) {
                        int col = c0 + cb;
                        int h = col >> 6, w = col & 63;
                        int pc2 = ((((h & 1) << 1) | (w & 1)) << 10) | ((h >> 1) << 5) | (w >> 1);
                        Y[((size_t)b * M + m) * HWN + pc2] = cb ? v1 : v0;
                    }
                } else {
                    float2* yp = reinterpret_cast<float2*>(&Y[((size_t)b * M + m) * HWN + c0]);
                    if (EP == E_RESID) {
                        float2 o = *yp;
                        o.x += v0; o.y += v1;
                        *yp = o;
                    } else {
                        *yp = make_float2(v0, v1);
                    }
                }
            }
        }
}

// ---------------- host ----------------
template<int EP, int NPL>
static void launch15(int woff, const __half* Bh, const __half* Bl,
                     float* Y, const float* bias, int M, int K)
{
    cudaFuncSetAttribute(gemm15<EP, NPL>, cudaFuncAttributeMaxDynamicSharedMemorySize, G15_SMEM);
    gemm15<EP, NPL><<<dim3(32, M / 128, BB), 512, G15_SMEM>>>(woff, Bh, Bl, Y, bias, M, K);
}

extern "C" void kernel_launch(void* const* d_in, const int* in_sizes, int n_in,
                              void* d_out, int out_size)
{
    const float* x     = (const float*)d_in[0];
    const float* dw_w  = (const float*)d_in[1];
    const float* bn1_g = (const float*)d_in[2];
    const float* bn1_b = (const float*)d_in[3];
    const float* bn1_m = (const float*)d_in[4];
    const float* bn1_v = (const float*)d_in[5];
    const float* c1_w  = (const float*)d_in[6];
    const float* c1_b  = (const float*)d_in[7];
    const float* ln1_g = (const float*)d_in[8];
    const float* ln1_b = (const float*)d_in[9];
    const float* qkv_w = (const float*)d_in[10];
    const float* qkv_b = (const float*)d_in[11];
    const float* out_w = (const float*)d_in[12];
    const float* out_b = (const float*)d_in[13];
    const float* ln2_g = (const float*)d_in[14];
    const float* ln2_b = (const float*)d_in[15];
    const float* f1_w  = (const float*)d_in[16];
    const float* f1_b  = (const float*)d_in[17];
    const float* f2_w  = (const float*)d_in[18];
    const float* f2_b  = (const float*)d_in[19];
    const float* lnf_g = (const float*)d_in[20];
    const float* lnf_b = (const float*)d_in[21];
    const float* projw = (const float*)d_in[22];
    const float* bn2_g = (const float*)d_in[23];
    const float* bn2_b = (const float*)d_in[24];
    const float* bn2_m = (const float*)d_in[25];
    const float* bn2_v = (const float*)d_in[26];
    float* out = (float*)d_out;

    void* vp;
    cudaGetSymbolAddress(&vp, g_p);   float* p  = (float*)vp;
    cudaGetSymbolAddress(&vp, g_kv);  float* kv = (float*)vp;
    cudaGetSymbolAddress(&vp, g_zth); __half* zth = (__half*)vp;
    cudaGetSymbolAddress(&vp, g_ztl); __half* ztl = (__half*)vp;
    cudaGetSymbolAddress(&vp, g_hth); __half* hth = (__half*)vp;
    cudaGetSymbolAddress(&vp, g_yth); __half* yth = (__half*)vp;
    cudaGetSymbolAddress(&vp, g_ytl); __half* ytl = (__half*)vp;

    // single weight-convert launch (also folds BN2)
    WArgs wa;
    const float* qw0 = qkv_w;
    const float* qw1 = qkv_w + (size_t)513 * DD;
    const float* srcs[10] = {
        c1_w,
        qw0 + DD, out_w, f1_w, f2_w,
        qw1 + DD, out_w + (size_t)DD * DD, f1_w + (size_t)FF_ * DD, f2_w + (size_t)DD * FF_,
        projw };
    int Ks[10]   = {128, 256, 256, 256, 512, 256, 256, 256, 512, 256};
    int offs[10] = {OFF_C1, OFF_KV(0), OFF_OUT(0), OFF_F1(0), OFF_F2(0),
                    OFF_KV(1), OFF_OUT(1), OFF_F1(1), OFF_F2(1), OFF_PROJ};
    int rows[10] = {256, 512, 256, 512, 256, 512, 256, 512, 256, 128};
    int acc = 0;
    for (int i = 0; i < 10; i++) {
        wa.src[i] = srcs[i]; wa.K[i] = Ks[i]; wa.off[i] = offs[i];
        wa.row0[i] = acc; acc += rows[i];
    }
    wa.row0[10] = acc;  // 3456
    wsplit_all<<<3457, 128>>>(wa, bn2_g, bn2_b, bn2_m, bn2_v);

    dwconv_k<<<dim3(16, CC, BB), 256>>>(x, dw_w, bn1_g, bn1_b, bn1_m, bn1_v, kv);
    ypack_k<<<dim3(128, BB), dim3(32, 8)>>>(kv);

    // c1: p = patchify(W_c1 @ y + b)   (main stream: keep 2-plane)
    launch15<E_PERM_P, 2>(OFF_C1, yth, ytl, p, c1_b, DD, 128);

    for (int l = 0; l < 2; l++) {
        const float* qw  = qkv_w + (size_t)l * 513 * DD;
        const float* qbi = qkv_b + l * 513;

        colstats_k<<<dim3(128, BB), dim3(32, 8)>>>(p, ln1_g + l * DD, ln1_b + l * DD);
        launch15<E_KV, 2>(OFF_KV(l), zth, ztl, kv, qbi + 1, 512, 256);
        qsoftctx_k<<<128, 256>>>(qw, qbi);
        vctx_k<<<dim3(128, BB), dim3(32, 8)>>>();
        // attn delta -> residual-diluted: single plane
        launch15<E_RESID, 1>(OFF_OUT(l), zth, nullptr, p, out_b + l * DD, DD, 256);

        colstats_k<<<dim3(128, BB), dim3(32, 8)>>>(p, ln2_g + l * DD, ln2_b + l * DD);
        // FFN delta -> residual-diluted: single plane both legs
        launch15<E_H, 1>(OFF_F1(l), zth, nullptr, nullptr, f1_b + l * FF_, FF_, 256);
        launch15<E_RESID, 1>(OFF_F2(l), hth, nullptr, p, f2_b + l * DD, DD, 512);
    }

    colstats_k<<<dim3(128, BB), dim3(32, 8)>>>(p, lnf_g, lnf_b);
    launch15<E_OUT, 2>(OFF_PROJ, zth, ztl, out, nullptr, CC, 256);
}

// round 16
// speedup vs baseline: 1.4659x; 1.0644x over previous
#include <cuda_runtime.h>
#include <cuda_fp16.h>
#include <cstdint>

#define BB   32
#define CC   128
#define DD   256
#define FF_  512
#define HWN  4096
#define EPS  1e-5f

// ---------------- scratch ----------------
__device__ float g_p  [(size_t)BB * DD  * HWN];    // token tensor fp32
__device__ float g_kv [(size_t)BB * 512 * HWN];    // k|v fp32 (also dwconv temp)
__device__ float g_ctx[BB * 4 * DD];
__device__ float g_s2[CC], g_b2[CC];

// transposed fp16 hi/lo activation planes, [b][col][k]
__device__ __half g_zth[(size_t)BB * HWN * DD ];
__device__ __half g_ztl[(size_t)BB * HWN * DD ];
__device__ __half g_hth[(size_t)BB * HWN * FF_];   // h: single plane
__device__ __half g_yth[(size_t)BB * HWN * CC ];
__device__ __half g_ytl[(size_t)BB * HWN * CC ];

#define WTOT 983040
__device__ __half g_whi[WTOT];          // single-plane fp16 weights
#define OFF_C1    0
#define LSTRIDE   458752
#define OFF_KV(l)  (32768 + (l) * LSTRIDE)
#define OFF_OUT(l) (OFF_KV(l) + 131072)
#define OFF_F1(l)  (OFF_KV(l) + 196608)
#define OFF_F2(l)  (OFF_KV(l) + 327680)
#define OFF_PROJ  (32768 + 2 * LSTRIDE)

__device__ __forceinline__ void split_pair(float a, float b, uint32_t& h, uint32_t& l) {
    __half ha = __float2half_rn(a), hb = __float2half_rn(b);
    h = (uint32_t)__half_as_ushort(ha) | ((uint32_t)__half_as_ushort(hb) << 16);
    __half la = __float2half_rn(a - __half2float(ha));
    __half lb = __float2half_rn(b - __half2float(hb));
    l = (uint32_t)__half_as_ushort(la) | ((uint32_t)__half_as_ushort(lb) << 16);
}
__device__ __forceinline__ uint32_t pack_hi(float a, float b) {
    __half ha = __float2half_rn(a), hb = __float2half_rn(b);
    return (uint32_t)__half_as_ushort(ha) | ((uint32_t)__half_as_ushort(hb) << 16);
}
__device__ __forceinline__ float2 up2(uint32_t v) {
    __half2 t = *reinterpret_cast<const __half2*>(&v);
    return __half22float2(t);
}

// ---------------- wsplit_all: all weights (fp16) + BN2 prep, ONE launch -----
struct WArgs {
    const float* src[10];
    int K[10];
    int off[10];
    int row0[11];
};
__global__ void __launch_bounds__(128) wsplit_all(
    WArgs a, const float* bg, const float* bb, const float* bm, const float* bv)
{
    int blk = blockIdx.x;
    if (blk == 3456) {
        int i = threadIdx.x;
        if (i < CC) {
            float s = bg[i] * rsqrtf(bv[i] + EPS);
            g_s2[i] = s; g_b2[i] = bb[i] - bm[i] * s;
        }
        return;
    }
    int s = 0;
    while (blk >= a.row0[s + 1]) s++;
    int row = blk - a.row0[s];
    int K = a.K[s];
    const float* src = a.src[s] + (size_t)row * K;
    __half* dh = g_whi + a.off[s] + (size_t)row * K;
    for (int k = threadIdx.x; k < K; k += 128)
        dh[k] = __float2half_rn(src[k]);
}

// ---------------- dwconv3x3 + BN1 + leaky (fp32 temp) ----------------
__global__ void __launch_bounds__(256) dwconv_k(
    const float* __restrict__ x, const float* __restrict__ w,
    const float* __restrict__ bg, const float* __restrict__ bbias,
    const float* __restrict__ bm, const float* __restrict__ bv, float* __restrict__ yout)
{
    int b = blockIdx.z, c = blockIdx.y;
    int idx = blockIdx.x * 256 + threadIdx.x;
    __shared__ float ws[9]; __shared__ float sc, sh;
    if (threadIdx.x < 9) ws[threadIdx.x] = w[c * 9 + threadIdx.x];
    if (threadIdx.x == 0) {
        float s = bg[c] * rsqrtf(bv[c] + EPS);
        sc = s; sh = bbias[c] - bm[c] * s;
    }
    __syncthreads();
    int h = idx >> 6, wq = idx & 63;
    const float* xp = x + ((size_t)b * CC + c) * HWN;
    float acc = 0.f;
#pragma unroll
    for (int dh = 0; dh < 3; dh++) {
        int hh = h + dh - 1;
        if (hh < 0 || hh >= 64) continue;
#pragma unroll
        for (int dw = 0; dw < 3; dw++) {
            int w2 = wq + dw - 1;
            if (w2 < 0 || w2 >= 64) continue;
            acc = fmaf(xp[hh * 64 + w2], ws[dh * 3 + dw], acc);
        }
    }
    float o = acc * sc + sh;
    o = (o > 0.f) ? o : 0.1f * o;
    yout[((size_t)b * CC + c) * HWN + idx] = o;
}

// ---------------- y fp32 [c][pix] -> yt planes [pix][128] ----------------
__global__ void __launch_bounds__(256) ypack_k(const float* __restrict__ y)
{
    int b = blockIdx.y, tx = threadIdx.x, ty = threadIdx.y;
    int p0 = blockIdx.x * 32;
    __shared__ float sy[128][33];
    for (int ct = 0; ct < 4; ct++)
#pragma unroll
        for (int q = 0; q < 4; q++) {
            int c = ct * 32 + ty * 4 + q;
            sy[c][tx] = y[((size_t)b * CC + c) * HWN + p0 + tx];
        }
    __syncthreads();
    uint32_t wh[8], wl[8];
#pragma unroll
    for (int j = 0; j < 16; j += 2)
        split_pair(sy[ty * 16 + j][tx], sy[ty * 16 + j + 1][tx], wh[j >> 1], wl[j >> 1]);
    size_t o = ((size_t)b * HWN + p0 + tx) * CC + ty * 16;
    uint4* dh = reinterpret_cast<uint4*>(g_yth + o);
    uint4* dl = reinterpret_cast<uint4*>(g_ytl + o);
    dh[0] = make_uint4(wh[0], wh[1], wh[2], wh[3]);
    dh[1] = make_uint4(wh[4], wh[5], wh[6], wh[7]);
    dl[0] = make_uint4(wl[0], wl[1], wl[2], wl[3]);
    dl[1] = make_uint4(wl[4], wl[5], wl[6], wl[7]);
}

// ---------------- colstats + LN -> z planes [col][256] ----------------
__global__ void __launch_bounds__(256) colstats_k(
    const float* __restrict__ p,
    const float* __restrict__ lng, const float* __restrict__ lnb)
{
    int b = blockIdx.y, tx = threadIdx.x, ty = threadIdx.y;
    int col = blockIdx.x * 32 + tx;
    int lt = ty * 32 + tx;
    __shared__ float sg[256], sb[256];
    sg[lt] = lng[lt]; sb[lt] = lnb[lt];
    size_t base = (size_t)b * DD * HWN + col;
    float vals[32], s = 0.f, s2 = 0.f;
#pragma unroll
    for (int j = 0; j < 32; j++) {
        float v = p[base + ((size_t)(ty * 32 + j) << 12)];
        vals[j] = v; s += v; s2 = fmaf(v, v, s2);
    }
    __shared__ float sh1[8][32], sh2[8][32], smean[32], srstd[32];
    sh1[ty][tx] = s; sh2[ty][tx] = s2;
    __syncthreads();
    if (ty == 0) {
        float a = 0.f, a2 = 0.f;
#pragma unroll
        for (int k = 0; k < 8; k++) { a += sh1[k][tx]; a2 += sh2[k][tx]; }
        float mean = a * (1.f / DD);
        smean[tx] = mean;
        srstd[tx] = rsqrtf(a2 * (1.f / DD) - mean * mean + EPS);
    }
    __syncthreads();
    float mean = smean[tx], rstd = srstd[tx];
    uint32_t wh[16], wl[16];
#pragma unroll
    for (int j = 0; j < 32; j += 2) {
        int d = ty * 32 + j;
        float z0 = (vals[j]     - mean) * rstd * sg[d]     + sb[d];
        float z1 = (vals[j + 1] - mean) * rstd * sg[d + 1] + sb[d + 1];
        split_pair(z0, z1, wh[j >> 1], wl[j >> 1]);
    }
    size_t o = ((size_t)b * HWN + col) * DD + ty * 32;
    uint4* dh = reinterpret_cast<uint4*>(g_zth + o);
    uint4* dl = reinterpret_cast<uint4*>(g_ztl + o);
#pragma unroll
    for (int q = 0; q < 4; q++) {
        dh[q] = make_uint4(wh[4*q], wh[4*q+1], wh[4*q+2], wh[4*q+3]);
        dl[q] = make_uint4(wl[4*q], wl[4*q+1], wl[4*q+2], wl[4*q+3]);
    }
}

// ---------------- relu(v)*ctx -> z hi plane only [n][256] ----------------
__global__ void __launch_bounds__(256) vctx_k()
{
    int b = blockIdx.y, tx = threadIdx.x, ty = threadIdx.y;
    int n0 = blockIdx.x * 32;
    int pq = n0 >> 10;
    __shared__ float sv[256][33];
    for (int dt = 0; dt < 8; dt++)
#pragma unroll
        for (int q = 0; q < 4; q++) {
            int d = dt * 32 + ty * 4 + q;
            float v = g_kv[((size_t)b * 512 + 256 + d) * HWN + n0 + tx];
            sv[d][tx] = fmaxf(v, 0.f) * g_ctx[(b << 10) + (pq << 8) + d];
        }
    __syncthreads();
    uint32_t wh[16];
#pragma unroll
    for (int j = 0; j < 32; j += 2)
        wh[j >> 1] = pack_hi(sv[ty * 32 + j][tx], sv[ty * 32 + j + 1][tx]);
    size_t o = ((size_t)b * HWN + n0 + tx) * DD + ty * 32;
    uint4* dh = reinterpret_cast<uint4*>(g_zth + o);
#pragma unroll
    for (int q = 0; q < 4; q++)
        dh[q] = make_uint4(wh[4*q], wh[4*q+1], wh[4*q+2], wh[4*q+3]);
}

// ---------------- q-GEMV + softmax + ctx ----------------
__global__ void __launch_bounds__(256) qsoftctx_k(
    const float* __restrict__ wq, const float* __restrict__ qb)
{
    __shared__ float sprob[1024], wqs[256], red[256];
    int tid = threadIdx.x;
    int b = blockIdx.x >> 2, pq = blockIdx.x & 3;
    wqs[tid] = wq[tid];
    __syncthreads();
    float q0 = qb[0], qv[4];
#pragma unroll
    for (int r = 0; r < 4; r++) {
        int n = tid + (r << 8);
        size_t base = ((size_t)b * HWN + pq * 1024 + n) * DD;
        const uint4* zh = reinterpret_cast<const uint4*>(g_zth + base);
        const uint4* zl = reinterpret_cast<const uint4*>(g_ztl + base);
        float acc = q0;
#pragma unroll 4
        for (int i = 0; i < 32; i++) {
            uint4 H = zh[i], L = zl[i];
            const float* w8 = wqs + i * 8;
            float2 h0 = up2(H.x), l0 = up2(L.x), h1 = up2(H.y), l1 = up2(L.y);
            float2 h2 = up2(H.z), l2 = up2(L.z), h3 = up2(H.w), l3 = up2(L.w);
            acc = fmaf(w8[0], h0.x + l0.x, acc); acc = fmaf(w8[1], h0.y + l0.y, acc);
            acc = fmaf(w8[2], h1.x + l1.x, acc); acc = fmaf(w8[3], h1.y + l1.y, acc);
            acc = fmaf(w8[4], h2.x + l2.x, acc); acc = fmaf(w8[5], h2.y + l2.y, acc);
            acc = fmaf(w8[6], h3.x + l3.x, acc); acc = fmaf(w8[7], h3.y + l3.y, acc);
        }
        qv[r] = acc;
    }
    float lm = fmaxf(fmaxf(qv[0], qv[1]), fmaxf(qv[2], qv[3]));
    red[tid] = lm; __syncthreads();
    for (int s = 128; s > 0; s >>= 1) { if (tid < s) red[tid] = fmaxf(red[tid], red[tid+s]); __syncthreads(); }
    float gm = red[0]; __syncthreads();
    float e[4], ls = 0.f;
#pragma unroll
    for (int r = 0; r < 4; r++) { e[r] = __expf(qv[r] - gm); ls += e[r]; }
    red[tid] = ls; __syncthreads();
    for (int s = 128; s > 0; s >>= 1) { if (tid < s) red[tid] += red[tid+s]; __syncthreads(); }
    float inv = 1.f / red[0];
#pragma unroll
    for (int r = 0; r < 4; r++) sprob[tid + (r << 8)] = e[r] * inv;
    __syncthreads();
    int warp = tid >> 5, lane = tid & 31;
    for (int d = warp; d < 256; d += 8) {
        const float* kr = g_kv + ((size_t)b * 512 + d) * HWN + pq * 1024;
        float acc = 0.f;
#pragma unroll 8
        for (int n = lane; n < 1024; n += 32) acc = fmaf(kr[n], sprob[n], acc);
#pragma unroll
        for (int o = 16; o > 0; o >>= 1) acc += __shfl_down_sync(0xffffffffu, acc, o);
        if (lane == 0) g_ctx[(b << 10) + (pq << 8) + d] = acc;
    }
}

// ============================================================================
// fp16 GEMM v16: W single-plane; B hi/lo (NPL=2) or single-plane (NPL=1)
// 512 threads, 16 warps of 32x32, CTA 128x128, k-tile 32, cp.async 3-stage
// smem stage 24KB: A 8K | Bh 8K | Bl 8K (Bl slot unused when NPL=1)
// ============================================================================
__device__ __forceinline__ uint32_t smem_u32(const void* p) {
    uint32_t a;
    asm("{ .reg .u64 t; cvta.to.shared.u64 t, %1; cvt.u32.u64 %0, t; }" : "=r"(a) : "l"(p));
    return a;
}
#define LDSM4(R, A)                                                            \
    asm volatile("ldmatrix.sync.aligned.m8n8.x4.shared.b16 {%0,%1,%2,%3}, [%4];" \
        : "=r"((R)[0]), "=r"((R)[1]), "=r"((R)[2]), "=r"((R)[3]) : "r"(A))
#define HMMA32(D, A, B0, B1)                                                   \
    asm volatile("mma.sync.aligned.m16n8k16.row.col.f32.f16.f16.f32 "          \
        "{%0,%1,%2,%3},{%4,%5,%6,%7},{%8,%9},{%0,%1,%2,%3};"                   \
        : "+f"((D)[0]), "+f"((D)[1]), "+f"((D)[2]), "+f"((D)[3])               \
        : "r"((A)[0]), "r"((A)[1]), "r"((A)[2]), "r"((A)[3]), "r"(B0), "r"(B1))
#define CPA(D, S) asm volatile("cp.async.cg.shared.global [%0], [%1], 16;" :: "r"(D), "l"(S))

enum { E_KV = 0, E_RESID = 1, E_PERM_P = 2, E_OUT = 3, E_H = 4 };
#define G16_SMEM 73728   // 3 stages x 24KB

__device__ __forceinline__ uint32_t swz(int r, int c) {
    return (uint32_t)(r * 64 + ((c ^ ((r >> 1) & 3)) << 4));
}

template<int EP, int NPL>
__global__ void __launch_bounds__(512, 2) gemm16(
    int woff, const __half* __restrict__ Bhp, const __half* __restrict__ Blp,
    float* __restrict__ Y, const float* __restrict__ bias, int M, int K)
{
    extern __shared__ __align__(16) char smc[];
    const uint32_t sma = smem_u32(smc);
    const int tid = threadIdx.x, wid = tid >> 5, lane = tid & 31;
    const int gid = lane >> 2, tig = lane & 3;
    const int b = blockIdx.z, colT = blockIdx.x << 7, rowT = blockIdx.y << 7;
    const int mw = (wid & 3) << 5, nw = (wid >> 2) << 5;
    const int nT = K >> 5;

    const __half* gAh = g_whi + woff;

    float acc[2][4][4];
#pragma unroll
    for (int i = 0; i < 2; i++)
#pragma unroll
        for (int j = 0; j < 4; j++)
#pragma unroll
            for (int k = 0; k < 4; k++) acc[i][j][k] = 0.f;

    const int pr = tid >> 2, pc = tid & 3;

    auto issue = [&](int c) {
        uint32_t base = sma + (c % 3) * 24576;
        int k0 = c << 5;
        uint32_t sw = swz(pr, pc);
        size_t ga = (size_t)(rowT + pr) * K + k0 + pc * 8;
        size_t gb = ((size_t)b * HWN + colT + pr) * K + k0 + pc * 8;
        CPA(base + sw,        gAh + ga);
        CPA(base + 8192 + sw, Bhp + gb);
        if (NPL == 2) CPA(base + 16384 + sw, Blp + gb);
        asm volatile("cp.async.commit_group;");
    };

    issue(0);
    if (nT > 1) issue(1);
    for (int c = 0; c < nT; c++) {
        if (c + 1 < nT) asm volatile("cp.async.wait_group 1;");
        else            asm volatile("cp.async.wait_group 0;");
        __syncthreads();
        if (c + 2 < nT) issue(c + 2);
        uint32_t sb = sma + (c % 3) * 24576;
#pragma unroll
        for (int h = 0; h < 2; h++) {
            int cc = h * 2 + (lane >> 4);
            uint32_t Ah[2][4];
#pragma unroll
            for (int mi = 0; mi < 2; mi++) {
                int r = mw + mi * 16 + (lane & 15);
                LDSM4(Ah[mi], sb + swz(r, cc));
            }
#pragma unroll
            for (int p = 0; p < 2; p++) {
                uint32_t Bh[4], Bl[4];
                int r = nw + p * 16 + (lane & 15);
                uint32_t ad = sb + 8192 + swz(r, cc);
                LDSM4(Bh, ad);
                if (NPL == 2) LDSM4(Bl, ad + 8192);
#pragma unroll
                for (int mi = 0; mi < 2; mi++)
#pragma unroll
                    for (int q = 0; q < 2; q++) {
                        int ni = p * 2 + q;
                        HMMA32(acc[mi][ni], Ah[mi], Bh[q], Bh[q + 2]);
                        if (NPL == 2) HMMA32(acc[mi][ni], Ah[mi], Bl[q], Bl[q + 2]);
                    }
            }
        }
    }

    // ---- epilogue ----
    if (EP == E_H) {
        // leaky + fp16 (single plane), smem transpose -> g_hth [col][FF_]
        __syncthreads();
        __half* trh = reinterpret_cast<__half*>(smc);
#pragma unroll
        for (int mi = 0; mi < 2; mi++) {
            float bi0 = bias[rowT + mw + mi * 16 + gid];
            float bi1 = bias[rowT + mw + mi * 16 + gid + 8];
#pragma unroll
            for (int ni = 0; ni < 4; ni++)
#pragma unroll
                for (int r = 0; r < 4; r++) {
                    float v = acc[mi][ni][r] + ((r >> 1) ? bi1 : bi0);
                    v = (v > 0.f) ? v : 0.1f * v;
                    int ml = mw + mi * 16 + gid + (r >> 1) * 8;
                    int nl = nw + ni * 8 + tig * 2 + (r & 1);
                    trh[nl * 136 + ml] = __float2half_rn(v);
                }
        }
        __syncthreads();
        int nl = tid >> 2, qt = tid & 3;
        const uint4* s1 = reinterpret_cast<const uint4*>(trh + nl * 136 + qt * 32);
        size_t o = ((size_t)b * HWN + colT + nl) * FF_ + rowT + qt * 32;
        uint4* d1 = reinterpret_cast<uint4*>(g_hth + o);
#pragma unroll
        for (int j = 0; j < 4; j++) d1[j] = s1[j];
        return;
    }

#pragma unroll
    for (int mi = 0; mi < 2; mi++)
#pragma unroll
        for (int r2 = 0; r2 < 2; r2++) {
            int m = rowT + mw + mi * 16 + gid + r2 * 8;
            float bi = (EP == E_OUT) ? 0.f : bias[m];
#pragma unroll
            for (int ni = 0; ni < 4; ni++) {
                int c0 = colT + nw + ni * 8 + tig * 2;
                float v0 = acc[mi][ni][r2 * 2 + 0] + bi;
                float v1 = acc[mi][ni][r2 * 2 + 1] + bi;
                if (EP == E_OUT) {
                    float rs = g_s2[m], rb = g_b2[m];
                    v0 = v0 * rs + rb; v1 = v1 * rs + rb;
                    float* yb = Y + ((size_t)b * CC + m) * HWN;
#pragma unroll
                    for (int cb = 0; cb < 2; cb++) {
                        int col = c0 + cb;
                        int pq = col >> 10, n = col & 1023;
                        int h = ((n >> 5) << 1) | (pq >> 1);
                        int w2 = ((n & 31) << 1) | (pq & 1);
                        yb[h * 64 + w2] = cb ? v1 : v0;
                    }
                } else if (EP == E_PERM_P) {
#pragma unroll
                    for (int cb = 0; cb < 2; cb++) {
                        int col = c0 + cb;
                        int h = col >> 6, w = col & 63;
                        int pc2 = ((((h & 1) << 1) | (w & 1)) << 10) | ((h >> 1) << 5) | (w >> 1);
                        Y[((size_t)b * M + m) * HWN + pc2] = cb ? v1 : v0;
                    }
                } else {
                    float2* yp = reinterpret_cast<float2*>(&Y[((size_t)b * M + m) * HWN + c0]);
                    if (EP == E_RESID) {
                        float2 o = *yp;
                        o.x += v0; o.y += v1;
                        *yp = o;
                    } else {
                        *yp = make_float2(v0, v1);
                    }
                }
            }
        }
}

// ---------------- host ----------------
template<int EP, int NPL>
static void launch16(int woff, const __half* Bh, const __half* Bl,
                     float* Y, const float* bias, int M, int K)
{
    cudaFuncSetAttribute(gemm16<EP, NPL>, cudaFuncAttributeMaxDynamicSharedMemorySize, G16_SMEM);
    gemm16<EP, NPL><<<dim3(32, M / 128, BB), 512, G16_SMEM>>>(woff, Bh, Bl, Y, bias, M, K);
}

extern "C" void kernel_launch(void* const* d_in, const int* in_sizes, int n_in,
                              void* d_out, int out_size)
{
    const float* x     = (const float*)d_in[0];
    const float* dw_w  = (const float*)d_in[1];
    const float* bn1_g = (const float*)d_in[2];
    const float* bn1_b = (const float*)d_in[3];
    const float* bn1_m = (const float*)d_in[4];
    const float* bn1_v = (const float*)d_in[5];
    const float* c1_w  = (const float*)d_in[6];
    const float* c1_b  = (const float*)d_in[7];
    const float* ln1_g = (const float*)d_in[8];
    const float* ln1_b = (const float*)d_in[9];
    const float* qkv_w = (const float*)d_in[10];
    const float* qkv_b = (const float*)d_in[11];
    const float* out_w = (const float*)d_in[12];
    const float* out_b = (const float*)d_in[13];
    const float* ln2_g = (const float*)d_in[14];
    const float* ln2_b = (const float*)d_in[15];
    const float* f1_w  = (const float*)d_in[16];
    const float* f1_b  = (const float*)d_in[17];
    const float* f2_w  = (const float*)d_in[18];
    const float* f2_b  = (const float*)d_in[19];
    const float* lnf_g = (const float*)d_in[20];
    const float* lnf_b = (const float*)d_in[21];
    const float* projw = (const float*)d_in[22];
    const float* bn2_g = (const float*)d_in[23];
    const float* bn2_b = (const float*)d_in[24];
    const float* bn2_m = (const float*)d_in[25];
    const float* bn2_v = (const float*)d_in[26];
    float* out = (float*)d_out;

    void* vp;
    cudaGetSymbolAddress(&vp, g_p);   float* p  = (float*)vp;
    cudaGetSymbolAddress(&vp, g_kv);  float* kv = (float*)vp;
    cudaGetSymbolAddress(&vp, g_zth); __half* zth = (__half*)vp;
    cudaGetSymbolAddress(&vp, g_ztl); __half* ztl = (__half*)vp;
    cudaGetSymbolAddress(&vp, g_hth); __half* hth = (__half*)vp;
    cudaGetSymbolAddress(&vp, g_yth); __half* yth = (__half*)vp;
    cudaGetSymbolAddress(&vp, g_ytl); __half* ytl = (__half*)vp;

    // single weight-convert launch (also folds BN2)
    WArgs wa;
    const float* qw0 = qkv_w;
    const float* qw1 = qkv_w + (size_t)513 * DD;
    const float* srcs[10] = {
        c1_w,
        qw0 + DD, out_w, f1_w, f2_w,
        qw1 + DD, out_w + (size_t)DD * DD, f1_w + (size_t)FF_ * DD, f2_w + (size_t)DD * FF_,
        projw };
    int Ks[10]   = {128, 256, 256, 256, 512, 256, 256, 256, 512, 256};
    int offs[10] = {OFF_C1, OFF_KV(0), OFF_OUT(0), OFF_F1(0), OFF_F2(0),
                    OFF_KV(1), OFF_OUT(1), OFF_F1(1), OFF_F2(1), OFF_PROJ};
    int rows[10] = {256, 512, 256, 512, 256, 512, 256, 512, 256, 128};
    int acc = 0;
    for (int i = 0; i < 10; i++) {
        wa.src[i] = srcs[i]; wa.K[i] = Ks[i]; wa.off[i] = offs[i];
        wa.row0[i] = acc; acc += rows[i];
    }
    wa.row0[10] = acc;  // 3456
    wsplit_all<<<3457, 128>>>(wa, bn2_g, bn2_b, bn2_m, bn2_v);

    dwconv_k<<<dim3(16, CC, BB), 256>>>(x, dw_w, bn1_g, bn1_b, bn1_m, bn1_v, kv);
    ypack_k<<<dim3(128, BB), dim3(32, 8)>>>(kv);

    // c1: p = patchify(W_c1 @ y + b)   (main stream: keep 2-plane)
    launch16<E_PERM_P, 2>(OFF_C1, yth, ytl, p, c1_b, DD, 128);

    for (int l = 0; l < 2; l++) {
        const float* qw  = qkv_w + (size_t)l * 513 * DD;
        const float* qbi = qkv_b + l * 513;

        colstats_k<<<dim3(128, BB), dim3(32, 8)>>>(p, ln1_g + l * DD, ln1_b + l * DD);
        // kv feeds only the attention delta -> residual-diluted: single plane
        launch16<E_KV, 1>(OFF_KV(l), zth, nullptr, kv, qbi + 1, 512, 256);
        qsoftctx_k<<<128, 256>>>(qw, qbi);
        vctx_k<<<dim3(128, BB), dim3(32, 8)>>>();
        // attn delta -> residual-diluted: single plane
        launch16<E_RESID, 1>(OFF_OUT(l), zth, nullptr, p, out_b + l * DD, DD, 256);

        colstats_k<<<dim3(128, BB), dim3(32, 8)>>>(p, ln2_g + l * DD, ln2_b + l * DD);
        // FFN delta -> residual-diluted: single plane both legs
        launch16<E_H, 1>(OFF_F1(l), zth, nullptr, nullptr, f1_b + l * FF_, FF_, 256);
        launch16<E_RESID, 1>(OFF_F2(l), hth, nullptr, p, f2_b + l * DD, DD, 512);
    }

    colstats_k<<<dim3(128, BB), dim3(32, 8)>>>(p, lnf_g, lnf_b);
    launch16<E_OUT, 2>(OFF_PROJ, zth, ztl, out, nullptr, CC, 256);
}

// round 17
// speedup vs baseline: 1.6139x; 1.1010x over previous
#include <cuda_runtime.h>
#include <cuda_fp16.h>
#include <cstdint>

#define BB   32
#define CC   128
#define DD   256
#define FF_  512
#define HWN  4096
#define EPS  1e-5f

// ---------------- scratch ----------------
__device__ float g_p  [(size_t)BB * DD  * HWN];    // token tensor fp32
__device__ float g_kv [(size_t)BB * 512 * HWN];    // k|v fp32 (also dwconv temp)
__device__ float g_ctx[BB * 4 * DD];
__device__ float g_s2[CC], g_b2[CC];

// transposed fp16 activation planes (single plane), [b][col][k]
__device__ __half g_zth[(size_t)BB * HWN * DD ];
__device__ __half g_hth[(size_t)BB * HWN * FF_];
__device__ __half g_yth[(size_t)BB * HWN * CC ];

#define WTOT 983040
__device__ __half g_whi[WTOT];          // single-plane fp16 weights
#define OFF_C1    0
#define LSTRIDE   458752
#define OFF_KV(l)  (32768 + (l) * LSTRIDE)
#define OFF_OUT(l) (OFF_KV(l) + 131072)
#define OFF_F1(l)  (OFF_KV(l) + 196608)
#define OFF_F2(l)  (OFF_KV(l) + 327680)
#define OFF_PROJ  (32768 + 2 * LSTRIDE)

__device__ __forceinline__ uint32_t pack_hi(float a, float b) {
    __half ha = __float2half_rn(a), hb = __float2half_rn(b);
    return (uint32_t)__half_as_ushort(ha) | ((uint32_t)__half_as_ushort(hb) << 16);
}
__device__ __forceinline__ float2 up2(uint32_t v) {
    __half2 t = *reinterpret_cast<const __half2*>(&v);
    return __half22float2(t);
}

// ---------------- wsplit_all: all weights (fp16) + BN2 prep, ONE launch -----
struct WArgs {
    const float* src[10];
    int K[10];
    int off[10];
    int row0[11];
};
__global__ void __launch_bounds__(128) wsplit_all(
    WArgs a, const float* bg, const float* bb, const float* bm, const float* bv)
{
    int blk = blockIdx.x;
    if (blk == 3456) {
        int i = threadIdx.x;
        if (i < CC) {
            float s = bg[i] * rsqrtf(bv[i] + EPS);
            g_s2[i] = s; g_b2[i] = bb[i] - bm[i] * s;
        }
        return;
    }
    int s = 0;
    while (blk >= a.row0[s + 1]) s++;
    int row = blk - a.row0[s];
    int K = a.K[s];
    const float* src = a.src[s] + (size_t)row * K;
    __half* dh = g_whi + a.off[s] + (size_t)row * K;
    for (int k = threadIdx.x; k < K; k += 128)
        dh[k] = __float2half_rn(src[k]);
}

// ---------------- dwconv3x3 + BN1 + leaky (fp32 temp) ----------------
__global__ void __launch_bounds__(256) dwconv_k(
    const float* __restrict__ x, const float* __restrict__ w,
    const float* __restrict__ bg, const float* __restrict__ bbias,
    const float* __restrict__ bm, const float* __restrict__ bv, float* __restrict__ yout)
{
    int b = blockIdx.z, c = blockIdx.y;
    int idx = blockIdx.x * 256 + threadIdx.x;
    __shared__ float ws[9]; __shared__ float sc, sh;
    if (threadIdx.x < 9) ws[threadIdx.x] = w[c * 9 + threadIdx.x];
    if (threadIdx.x == 0) {
        float s = bg[c] * rsqrtf(bv[c] + EPS);
        sc = s; sh = bbias[c] - bm[c] * s;
    }
    __syncthreads();
    int h = idx >> 6, wq = idx & 63;
    const float* xp = x + ((size_t)b * CC + c) * HWN;
    float acc = 0.f;
#pragma unroll
    for (int dh = 0; dh < 3; dh++) {
        int hh = h + dh - 1;
        if (hh < 0 || hh >= 64) continue;
#pragma unroll
        for (int dw = 0; dw < 3; dw++) {
            int w2 = wq + dw - 1;
            if (w2 < 0 || w2 >= 64) continue;
            acc = fmaf(xp[hh * 64 + w2], ws[dh * 3 + dw], acc);
        }
    }
    float o = acc * sc + sh;
    o = (o > 0.f) ? o : 0.1f * o;
    yout[((size_t)b * CC + c) * HWN + idx] = o;
}

// ---------------- y fp32 [c][pix] -> yt plane [pix][128] ----------------
__global__ void __launch_bounds__(256) ypack_k(const float* __restrict__ y)
{
    int b = blockIdx.y, tx = threadIdx.x, ty = threadIdx.y;
    int p0 = blockIdx.x * 32;
    __shared__ float sy[128][33];
    for (int ct = 0; ct < 4; ct++)
#pragma unroll
        for (int q = 0; q < 4; q++) {
            int c = ct * 32 + ty * 4 + q;
            sy[c][tx] = y[((size_t)b * CC + c) * HWN + p0 + tx];
        }
    __syncthreads();
    uint32_t wh[8];
#pragma unroll
    for (int j = 0; j < 16; j += 2)
        wh[j >> 1] = pack_hi(sy[ty * 16 + j][tx], sy[ty * 16 + j + 1][tx]);
    size_t o = ((size_t)b * HWN + p0 + tx) * CC + ty * 16;
    uint4* dh = reinterpret_cast<uint4*>(g_yth + o);
    dh[0] = make_uint4(wh[0], wh[1], wh[2], wh[3]);
    dh[1] = make_uint4(wh[4], wh[5], wh[6], wh[7]);
}

// ---------------- colstats + LN -> z plane [col][256] ----------------
__global__ void __launch_bounds__(256) colstats_k(
    const float* __restrict__ p,
    const float* __restrict__ lng, const float* __restrict__ lnb)
{
    int b = blockIdx.y, tx = threadIdx.x, ty = threadIdx.y;
    int col = blockIdx.x * 32 + tx;
    int lt = ty * 32 + tx;
    __shared__ float sg[256], sb[256];
    sg[lt] = lng[lt]; sb[lt] = lnb[lt];
    size_t base = (size_t)b * DD * HWN + col;
    float vals[32], s = 0.f, s2 = 0.f;
#pragma unroll
    for (int j = 0; j < 32; j++) {
        float v = p[base + ((size_t)(ty * 32 + j) << 12)];
        vals[j] = v; s += v; s2 = fmaf(v, v, s2);
    }
    __shared__ float sh1[8][32], sh2[8][32], smean[32], srstd[32];
    sh1[ty][tx] = s; sh2[ty][tx] = s2;
    __syncthreads();
    if (ty == 0) {
        float a = 0.f, a2 = 0.f;
#pragma unroll
        for (int k = 0; k < 8; k++) { a += sh1[k][tx]; a2 += sh2[k][tx]; }
        float mean = a * (1.f / DD);
        smean[tx] = mean;
        srstd[tx] = rsqrtf(a2 * (1.f / DD) - mean * mean + EPS);
    }
    __syncthreads();
    float mean = smean[tx], rstd = srstd[tx];
    uint32_t wh[16];
#pragma unroll
    for (int j = 0; j < 32; j += 2) {
        int d = ty * 32 + j;
        float z0 = (vals[j]     - mean) * rstd * sg[d]     + sb[d];
        float z1 = (vals[j + 1] - mean) * rstd * sg[d + 1] + sb[d + 1];
        wh[j >> 1] = pack_hi(z0, z1);
    }
    size_t o = ((size_t)b * HWN + col) * DD + ty * 32;
    uint4* dh = reinterpret_cast<uint4*>(g_zth + o);
#pragma unroll
    for (int q = 0; q < 4; q++)
        dh[q] = make_uint4(wh[4*q], wh[4*q+1], wh[4*q+2], wh[4*q+3]);
}

// ---------------- relu(v)*ctx -> z plane (reused) [n][256] ----------------
__global__ void __launch_bounds__(256) vctx_k()
{
    int b = blockIdx.y, tx = threadIdx.x, ty = threadIdx.y;
    int n0 = blockIdx.x * 32;
    int pq = n0 >> 10;
    __shared__ float sv[256][33];
    for (int dt = 0; dt < 8; dt++)
#pragma unroll
        for (int q = 0; q < 4; q++) {
            int d = dt * 32 + ty * 4 + q;
            float v = g_kv[((size_t)b * 512 + 256 + d) * HWN + n0 + tx];
            sv[d][tx] = fmaxf(v, 0.f) * g_ctx[(b << 10) + (pq << 8) + d];
        }
    __syncthreads();
    uint32_t wh[16];
#pragma unroll
    for (int j = 0; j < 32; j += 2)
        wh[j >> 1] = pack_hi(sv[ty * 32 + j][tx], sv[ty * 32 + j + 1][tx]);
    size_t o = ((size_t)b * HWN + n0 + tx) * DD + ty * 32;
    uint4* dh = reinterpret_cast<uint4*>(g_zth + o);
#pragma unroll
    for (int q = 0; q < 4; q++)
        dh[q] = make_uint4(wh[4*q], wh[4*q+1], wh[4*q+2], wh[4*q+3]);
}

// ---------------- q-GEMV + softmax + ctx (single-plane z) ----------------
__global__ void __launch_bounds__(256) qsoftctx_k(
    const float* __restrict__ wq, const float* __restrict__ qb)
{
    __shared__ float sprob[1024], wqs[256], red[256];
    int tid = threadIdx.x;
    int b = blockIdx.x >> 2, pq = blockIdx.x & 3;
    wqs[tid] = wq[tid];
    __syncthreads();
    float q0 = qb[0], qv[4];
#pragma unroll
    for (int r = 0; r < 4; r++) {
        int n = tid + (r << 8);
        size_t base = ((size_t)b * HWN + pq * 1024 + n) * DD;
        const uint4* zh = reinterpret_cast<const uint4*>(g_zth + base);
        float acc = q0;
#pragma unroll 4
        for (int i = 0; i < 32; i++) {
            uint4 H = zh[i];
            const float* w8 = wqs + i * 8;
            float2 h0 = up2(H.x), h1 = up2(H.y), h2 = up2(H.z), h3 = up2(H.w);
            acc = fmaf(w8[0], h0.x, acc); acc = fmaf(w8[1], h0.y, acc);
            acc = fmaf(w8[2], h1.x, acc); acc = fmaf(w8[3], h1.y, acc);
            acc = fmaf(w8[4], h2.x, acc); acc = fmaf(w8[5], h2.y, acc);
            acc = fmaf(w8[6], h3.x, acc); acc = fmaf(w8[7], h3.y, acc);
        }
        qv[r] = acc;
    }
    float lm = fmaxf(fmaxf(qv[0], qv[1]), fmaxf(qv[2], qv[3]));
    red[tid] = lm; __syncthreads();
    for (int s = 128; s > 0; s >>= 1) { if (tid < s) red[tid] = fmaxf(red[tid], red[tid+s]); __syncthreads(); }
    float gm = red[0]; __syncthreads();
    float e[4], ls = 0.f;
#pragma unroll
    for (int r = 0; r < 4; r++) { e[r] = __expf(qv[r] - gm); ls += e[r]; }
    red[tid] = ls; __syncthreads();
    for (int s = 128; s > 0; s >>= 1) { if (tid < s) red[tid] += red[tid+s]; __syncthreads(); }
    float inv = 1.f / red[0];
#pragma unroll
    for (int r = 0; r < 4; r++) sprob[tid + (r << 8)] = e[r] * inv;
    __syncthreads();
    int warp = tid >> 5, lane = tid & 31;
    for (int d = warp; d < 256; d += 8) {
        const float* kr = g_kv + ((size_t)b * 512 + d) * HWN + pq * 1024;
        float acc = 0.f;
#pragma unroll 8
        for (int n = lane; n < 1024; n += 32) acc = fmaf(kr[n], sprob[n], acc);
#pragma unroll
        for (int o = 16; o > 0; o >>= 1) acc += __shfl_down_sync(0xffffffffu, acc, o);
        if (lane == 0) g_ctx[(b << 10) + (pq << 8) + d] = acc;
    }
}

// ============================================================================
// fp16 GEMM v17: W single-plane; B single-plane (NPL=1 everywhere now)
// 512 threads, 16 warps of 32x32, CTA 128x128, k-tile 32, cp.async 3-stage
// smem stage 24KB: A 8K | Bh 8K | (spare 8K)
// ============================================================================
__device__ __forceinline__ uint32_t smem_u32(const void* p) {
    uint32_t a;
    asm("{ .reg .u64 t; cvta.to.shared.u64 t, %1; cvt.u32.u64 %0, t; }" : "=r"(a) : "l"(p));
    return a;
}
#define LDSM4(R, A)                                                            \
    asm volatile("ldmatrix.sync.aligned.m8n8.x4.shared.b16 {%0,%1,%2,%3}, [%4];" \
        : "=r"((R)[0]), "=r"((R)[1]), "=r"((R)[2]), "=r"((R)[3]) : "r"(A))
#define HMMA32(D, A, B0, B1)                                                   \
    asm volatile("mma.sync.aligned.m16n8k16.row.col.f32.f16.f16.f32 "          \
        "{%0,%1,%2,%3},{%4,%5,%6,%7},{%8,%9},{%0,%1,%2,%3};"                   \
        : "+f"((D)[0]), "+f"((D)[1]), "+f"((D)[2]), "+f"((D)[3])               \
        : "r"((A)[0]), "r"((A)[1]), "r"((A)[2]), "r"((A)[3]), "r"(B0), "r"(B1))
#define CPA(D, S) asm volatile("cp.async.cg.shared.global [%0], [%1], 16;" :: "r"(D), "l"(S))

enum { E_KV = 0, E_RESID = 1, E_PERM_P = 2, E_OUT = 3, E_H = 4 };
#define G17_SMEM 73728   // 3 stages x 24KB

__device__ __forceinline__ uint32_t swz(int r, int c) {
    return (uint32_t)(r * 64 + ((c ^ ((r >> 1) & 3)) << 4));
}

template<int EP>
__global__ void __launch_bounds__(512, 2) gemm17(
    int woff, const __half* __restrict__ Bhp,
    float* __restrict__ Y, const float* __restrict__ bias, int M, int K)
{
    extern __shared__ __align__(16) char smc[];
    const uint32_t sma = smem_u32(smc);
    const int tid = threadIdx.x, wid = tid >> 5, lane = tid & 31;
    const int gid = lane >> 2, tig = lane & 3;
    const int b = blockIdx.z, colT = blockIdx.x << 7, rowT = blockIdx.y << 7;
    const int mw = (wid & 3) << 5, nw = (wid >> 2) << 5;
    const int nT = K >> 5;

    const __half* gAh = g_whi + woff;

    float acc[2][4][4];
#pragma unroll
    for (int i = 0; i < 2; i++)
#pragma unroll
        for (int j = 0; j < 4; j++)
#pragma unroll
            for (int k = 0; k < 4; k++) acc[i][j][k] = 0.f;

    const int pr = tid >> 2, pc = tid & 3;

    auto issue = [&](int c) {
        uint32_t base = sma + (c % 3) * 24576;
        int k0 = c << 5;
        uint32_t sw = swz(pr, pc);
        size_t ga = (size_t)(rowT + pr) * K + k0 + pc * 8;
        size_t gb = ((size_t)b * HWN + colT + pr) * K + k0 + pc * 8;
        CPA(base + sw,        gAh + ga);
        CPA(base + 8192 + sw, Bhp + gb);
        asm volatile("cp.async.commit_group;");
    };

    issue(0);
    if (nT > 1) issue(1);
    for (int c = 0; c < nT; c++) {
        if (c + 1 < nT) asm volatile("cp.async.wait_group 1;");
        else            asm volatile("cp.async.wait_group 0;");
        __syncthreads();
        if (c + 2 < nT) issue(c + 2);
        uint32_t sb = sma + (c % 3) * 24576;
#pragma unroll
        for (int h = 0; h < 2; h++) {
            int cc = h * 2 + (lane >> 4);
            uint32_t Ah[2][4];
#pragma unroll
            for (int mi = 0; mi < 2; mi++) {
                int r = mw + mi * 16 + (lane & 15);
                LDSM4(Ah[mi], sb + swz(r, cc));
            }
#pragma unroll
            for (int p = 0; p < 2; p++) {
                uint32_t Bh[4];
                int r = nw + p * 16 + (lane & 15);
                LDSM4(Bh, sb + 8192 + swz(r, cc));
#pragma unroll
                for (int mi = 0; mi < 2; mi++)
#pragma unroll
                    for (int q = 0; q < 2; q++) {
                        int ni = p * 2 + q;
                        HMMA32(acc[mi][ni], Ah[mi], Bh[q], Bh[q + 2]);
                    }
            }
        }
    }

    // ---- epilogue ----
    if (EP == E_H) {
        __syncthreads();
        __half* trh = reinterpret_cast<__half*>(smc);
#pragma unroll
        for (int mi = 0; mi < 2; mi++) {
            float bi0 = bias[rowT + mw + mi * 16 + gid];
            float bi1 = bias[rowT + mw + mi * 16 + gid + 8];
#pragma unroll
            for (int ni = 0; ni < 4; ni++)
#pragma unroll
                for (int r = 0; r < 4; r++) {
                    float v = acc[mi][ni][r] + ((r >> 1) ? bi1 : bi0);
                    v = (v > 0.f) ? v : 0.1f * v;
                    int ml = mw + mi * 16 + gid + (r >> 1) * 8;
                    int nl = nw + ni * 8 + tig * 2 + (r & 1);
                    trh[nl * 136 + ml] = __float2half_rn(v);
                }
        }
        __syncthreads();
        int nl = tid >> 2, qt = tid & 3;
        const uint4* s1 = reinterpret_cast<const uint4*>(trh + nl * 136 + qt * 32);
        size_t o = ((size_t)b * HWN + colT + nl) * FF_ + rowT + qt * 32;
        uint4* d1 = reinterpret_cast<uint4*>(g_hth + o);
#pragma unroll
        for (int j = 0; j < 4; j++) d1[j] = s1[j];
        return;
    }

#pragma unroll
    for (int mi = 0; mi < 2; mi++)
#pragma unroll
        for (int r2 = 0; r2 < 2; r2++) {
            int m = rowT + mw + mi * 16 + gid + r2 * 8;
            float bi = (EP == E_OUT) ? 0.f : bias[m];
#pragma unroll
            for (int ni = 0; ni < 4; ni++) {
                int c0 = colT + nw + ni * 8 + tig * 2;
                float v0 = acc[mi][ni][r2 * 2 + 0] + bi;
                float v1 = acc[mi][ni][r2 * 2 + 1] + bi;
                if (EP == E_OUT) {
                    float rs = g_s2[m], rb = g_b2[m];
                    v0 = v0 * rs + rb; v1 = v1 * rs + rb;
                    float* yb = Y + ((size_t)b * CC + m) * HWN;
#pragma unroll
                    for (int cb = 0; cb < 2; cb++) {
                        int col = c0 + cb;
                        int pq = col >> 10, n = col & 1023;
                        int h = ((n >> 5) << 1) | (pq >> 1);
                        int w2 = ((n & 31) << 1) | (pq & 1);
                        yb[h * 64 + w2] = cb ? v1 : v0;
                    }
                } else if (EP == E_PERM_P) {
#pragma unroll
                    for (int cb = 0; cb < 2; cb++) {
                        int col = c0 + cb;
                        int h = col >> 6, w = col & 63;
                        int pc2 = ((((h & 1) << 1) | (w & 1)) << 10) | ((h >> 1) << 5) | (w >> 1);
                        Y[((size_t)b * M + m) * HWN + pc2] = cb ? v1 : v0;
                    }
                } else {
                    float2* yp = reinterpret_cast<float2*>(&Y[((size_t)b * M + m) * HWN + c0]);
                    if (EP == E_RESID) {
                        float2 o = *yp;
                        o.x += v0; o.y += v1;
                        *yp = o;
                    } else {
                        *yp = make_float2(v0, v1);
                    }
                }
            }
        }
}

// ---------------- host ----------------
template<int EP>
static void launch17(int woff, const __half* Bh,
                     float* Y, const float* bias, int M, int K)
{
    cudaFuncSetAttribute(gemm17<EP>, cudaFuncAttributeMaxDynamicSharedMemorySize, G17_SMEM);
    gemm17<EP><<<dim3(32, M / 128, BB), 512, G17_SMEM>>>(woff, Bh, Y, bias, M, K);
}

extern "C" void kernel_launch(void* const* d_in, const int* in_sizes, int n_in,
                              void* d_out, int out_size)
{
    const float* x     = (const float*)d_in[0];
    const float* dw_w  = (const float*)d_in[1];
    const float* bn1_g = (const float*)d_in[2];
    const float* bn1_b = (const float*)d_in[3];
    const float* bn1_m = (const float*)d_in[4];
    const float* bn1_v = (const float*)d_in[5];
    const float* c1_w  = (const float*)d_in[6];
    const float* c1_b  = (const float*)d_in[7];
    const float* ln1_g = (const float*)d_in[8];
    const float* ln1_b = (const float*)d_in[9];
    const float* qkv_w = (const float*)d_in[10];
    const float* qkv_b = (const float*)d_in[11];
    const float* out_w = (const float*)d_in[12];
    const float* out_b = (const float*)d_in[13];
    const float* ln2_g = (const float*)d_in[14];
    const float* ln2_b = (const float*)d_in[15];
    const float* f1_w  = (const float*)d_in[16];
    const float* f1_b  = (const float*)d_in[17];
    const float* f2_w  = (const float*)d_in[18];
    const float* f2_b  = (const float*)d_in[19];
    const float* lnf_g = (const float*)d_in[20];
    const float* lnf_b = (const float*)d_in[21];
    const float* projw = (const float*)d_in[22];
    const float* bn2_g = (const float*)d_in[23];
    const float* bn2_b = (const float*)d_in[24];
    const float* bn2_m = (const float*)d_in[25];
    const float* bn2_v = (const float*)d_in[26];
    float* out = (float*)d_out;

    void* vp;
    cudaGetSymbolAddress(&vp, g_p);   float* p  = (float*)vp;
    cudaGetSymbolAddress(&vp, g_kv);  float* kv = (float*)vp;
    cudaGetSymbolAddress(&vp, g_zth); __half* zth = (__half*)vp;
    cudaGetSymbolAddress(&vp, g_hth); __half* hth = (__half*)vp;
    cudaGetSymbolAddress(&vp, g_yth); __half* yth = (__half*)vp;

    // single weight-convert launch (also folds BN2)
    WArgs wa;
    const float* qw0 = qkv_w;
    const float* qw1 = qkv_w + (size_t)513 * DD;
    const float* srcs[10] = {
        c1_w,
        qw0 + DD, out_w, f1_w, f2_w,
        qw1 + DD, out_w + (size_t)DD * DD, f1_w + (size_t)FF_ * DD, f2_w + (size_t)DD * FF_,
        projw };
    int Ks[10]   = {128, 256, 256, 256, 512, 256, 256, 256, 512, 256};
    int offs[10] = {OFF_C1, OFF_KV(0), OFF_OUT(0), OFF_F1(0), OFF_F2(0),
                    OFF_KV(1), OFF_OUT(1), OFF_F1(1), OFF_F2(1), OFF_PROJ};
    int rows[10] = {256, 512, 256, 512, 256, 512, 256, 512, 256, 128};
    int acc = 0;
    for (int i = 0; i < 10; i++) {
        wa.src[i] = srcs[i]; wa.K[i] = Ks[i]; wa.off[i] = offs[i];
        wa.row0[i] = acc; acc += rows[i];
    }
    wa.row0[10] = acc;  // 3456
    wsplit_all<<<3457, 128>>>(wa, bn2_g, bn2_b, bn2_m, bn2_v);

    dwconv_k<<<dim3(16, CC, BB), 256>>>(x, dw_w, bn1_g, bn1_b, bn1_m, bn1_v, kv);
    ypack_k<<<dim3(128, BB), dim3(32, 8)>>>(kv);

    // c1: p = patchify(W_c1 @ y + b)
    launch17<E_PERM_P>(OFF_C1, yth, p, c1_b, DD, 128);

    for (int l = 0; l < 2; l++) {
        const float* qw  = qkv_w + (size_t)l * 513 * DD;
        const float* qbi = qkv_b + l * 513;

        colstats_k<<<dim3(128, BB), dim3(32, 8)>>>(p, ln1_g + l * DD, ln1_b + l * DD);
        launch17<E_KV>(OFF_KV(l), zth, kv, qbi + 1, 512, 256);
        qsoftctx_k<<<128, 256>>>(qw, qbi);
        vctx_k<<<dim3(128, BB), dim3(32, 8)>>>();
        launch17<E_RESID>(OFF_OUT(l), zth, p, out_b + l * DD, DD, 256);

        colstats_k<<<dim3(128, BB), dim3(32, 8)>>>(p, ln2_g + l * DD, ln2_b + l * DD);
        launch17<E_H>(OFF_F1(l), zth, nullptr, f1_b + l * FF_, FF_, 256);
        launch17<E_RESID>(OFF_F2(l), hth, p, f2_b + l * DD, DD, 512);
    }

    colstats_k<<<dim3(128, BB), dim3(32, 8)>>>(p, lnf_g, lnf_b);
    launch17<E_OUT>(OFF_PROJ, zth, out, nullptr, CC, 256);
}